// round 13
// baseline (speedup 1.0000x reference)
#include <cuda_runtime.h>
#include <cuda_bf16.h>
#include <cuda_fp16.h>
#include <math.h>
#include <stdint.h>

// ---------------------------------------------------------------------------
// GAT, 4 layers. N=50000, E=400000, F=256.
// Layers: 256->8x32, 256->4x32, 128->2x32, 64->1x32 (+ final log_softmax).
// ---------------------------------------------------------------------------
#define MAXN 50000
#define MAXE 400000

__device__ __half g_hf[MAXN * 256];            // h fp16 (agg gathers + self)
__device__ __nv_bfloat16 g_ah[MAXN * 256];     // layer input, bf16 high
__device__ __nv_bfloat16 g_al[MAXN * 256];     // layer input, bf16 low
__device__ __nv_bfloat16 g_wh[108544];         // all 4 W's, bf16 high
__device__ __nv_bfloat16 g_wl[108544];         // all 4 W's, bf16 low
__device__ float g_s[MAXN * 8];
__device__ float g_d[MAXN * 8];
__device__ float g_smax[32];                   // 4 layers x 8 heads
__device__ int   g_deg[MAXN];
__device__ int   g_rowptr[MAXN + 1];
__device__ int   g_cur[MAXN];
__device__ int   g_col[MAXE];
__device__ int   g_bsum[1024];
__device__ int   g_boff[1024];
__device__ int   g_is64;

// ---------------------------------------------------------------------------
// prep: all fp32 -> bf16(h,l) splits in one kernel + smax init
// ---------------------------------------------------------------------------
struct PrepArgs {
    const float* src[5];
    __nv_bfloat16* oh[5];
    __nv_bfloat16* ol[5];
    int start4[5];
    int total4;
};

__global__ void prep_kernel(PrepArgs a) {
    if (blockIdx.x == 0 && threadIdx.x < 32) g_smax[threadIdx.x] = -1e30f;
    int i = blockIdx.x * 256 + threadIdx.x;
    if (i >= a.total4) return;
    int seg = 0;
    #pragma unroll
    for (int k = 1; k < 5; ++k) if (i >= a.start4[k]) seg = k;
    int j = i - a.start4[seg];
    float4 f = reinterpret_cast<const float4*>(a.src[seg])[j];
    __nv_bfloat16 h0 = __float2bfloat16(f.x), h1 = __float2bfloat16(f.y);
    __nv_bfloat16 h2 = __float2bfloat16(f.z), h3 = __float2bfloat16(f.w);
    reinterpret_cast<__nv_bfloat162*>(a.oh[seg])[2 * j]     = __nv_bfloat162(h0, h1);
    reinterpret_cast<__nv_bfloat162*>(a.oh[seg])[2 * j + 1] = __nv_bfloat162(h2, h3);
    reinterpret_cast<__nv_bfloat162*>(a.ol[seg])[2 * j] = __nv_bfloat162(
        __float2bfloat16(f.x - __bfloat162float(h0)),
        __float2bfloat16(f.y - __bfloat162float(h1)));
    reinterpret_cast<__nv_bfloat162*>(a.ol[seg])[2 * j + 1] = __nv_bfloat162(
        __float2bfloat16(f.z - __bfloat162float(h2)),
        __float2bfloat16(f.w - __bfloat162float(h3)));
}

// ---------------------------------------------------------------------------
// CSR build (by dst)
// ---------------------------------------------------------------------------
__global__ void detzero_kernel(const int* __restrict__ ei32, int E, int N) {
    int i = blockIdx.x * blockDim.x + threadIdx.x;
    if (i < N) g_deg[i] = 0;
    if (blockIdx.x == 0 && threadIdx.x == 0) {
        int all_zero = 1;
        for (int k = 1; k < 64 && k < 2 * E; k += 2)
            if (ei32[k] != 0) { all_zero = 0; break; }
        g_is64 = all_zero;
    }
}

__device__ __forceinline__ int edge_val(const void* ei, int E, int which, int e) {
    if (g_is64) {
        const long long* p = (const long long*)ei;
        return (int)p[(size_t)which * E + e];
    } else {
        const int* p = (const int*)ei;
        return p[(size_t)which * E + e];
    }
}

__global__ void hist_kernel(const void* __restrict__ ei, int E) {
    int e = blockIdx.x * blockDim.x + threadIdx.x;
    if (e < E) atomicAdd(&g_deg[edge_val(ei, E, 1, e)], 1);
}

__global__ void scan1_kernel(int N) {
    __shared__ int ws[16];
    int tid = threadIdx.x;                 // 512 threads
    int lane = tid & 31, warp = tid >> 5;
    int i = blockIdx.x * 512 + tid;
    int v = (i < N) ? g_deg[i] : 0;
    int x = v;
    #pragma unroll
    for (int off = 1; off < 32; off <<= 1) {
        int y = __shfl_up_sync(0xFFFFFFFFu, x, off);
        if (lane >= off) x += y;
    }
    if (lane == 31) ws[warp] = x;
    __syncthreads();
    if (tid < 16) {
        int y = ws[tid];
        #pragma unroll
        for (int off = 1; off < 16; off <<= 1) {
            int z = __shfl_up_sync(0x0000FFFFu, y, off);
            if (tid >= off) y += z;
        }
        ws[tid] = y;
    }
    __syncthreads();
    int woff = (warp > 0) ? ws[warp - 1] : 0;
    if (i < N) g_rowptr[i] = x - v + woff;
    if (tid == 0) g_bsum[blockIdx.x] = ws[15];
}

__global__ void scan2_kernel(int nb, int N) {
    __shared__ int ws[4];
    int tid = threadIdx.x;                 // 128 threads, nb <= 128
    int lane = tid & 31, warp = tid >> 5;
    int v = (tid < nb) ? g_bsum[tid] : 0;
    int x = v;
    #pragma unroll
    for (int off = 1; off < 32; off <<= 1) {
        int y = __shfl_up_sync(0xFFFFFFFFu, x, off);
        if (lane >= off) x += y;
    }
    if (lane == 31) ws[warp] = x;
    __syncthreads();
    if (tid < 4) {
        int y = ws[tid];
        #pragma unroll
        for (int off = 1; off < 4; off <<= 1) {
            int z = __shfl_up_sync(0x0000000Fu, y, off);
            if (tid >= off) y += z;
        }
        ws[tid] = y;
    }
    __syncthreads();
    int woff = (warp > 0) ? ws[warp - 1] : 0;
    g_boff[tid] = x - v + woff;
    if (tid == 127) g_rowptr[N] = x + woff;
}

__global__ void scan3_kernel(int N) {
    int i = blockIdx.x * 512 + threadIdx.x;
    if (i < N) {
        int val = g_rowptr[i] + g_boff[blockIdx.x];
        g_rowptr[i] = val;
        g_cur[i] = val;
    }
}

__global__ void scatter_kernel(const void* __restrict__ ei, int E) {
    int e = blockIdx.x * blockDim.x + threadIdx.x;
    if (e < E) {
        int d = edge_val(ei, E, 1, e);
        int s = edge_val(ei, E, 0, e);
        g_col[atomicAdd(&g_cur[d], 1)] = s;
    }
}

__device__ __forceinline__ void atomicMaxFloat(float* addr, float val) {
    if (val >= 0.f) atomicMax((int*)addr, __float_as_int(val));
    else atomicMin((unsigned int*)addr, __float_as_uint(val));
}

// ---------------------------------------------------------------------------
// Tensor-core GEMM: BK=32, 2-stage cp.async, dynamic smem, fused sd/smax
// epilogue, fp16 output. C = Ah*Bh + Al*Bh + Ah*Bl (fp32 accum).
// ---------------------------------------------------------------------------
__device__ __forceinline__ void ldsm_x4(uint32_t& r0, uint32_t& r1, uint32_t& r2,
                                        uint32_t& r3, uint32_t addr) {
    asm volatile("ldmatrix.sync.aligned.m8n8.x4.shared.b16 {%0,%1,%2,%3}, [%4];\n"
                 : "=r"(r0), "=r"(r1), "=r"(r2), "=r"(r3) : "r"(addr));
}
__device__ __forceinline__ void ldsm_x4_t(uint32_t& r0, uint32_t& r1, uint32_t& r2,
                                          uint32_t& r3, uint32_t addr) {
    asm volatile("ldmatrix.sync.aligned.m8n8.x4.trans.shared.b16 {%0,%1,%2,%3}, [%4];\n"
                 : "=r"(r0), "=r"(r1), "=r"(r2), "=r"(r3) : "r"(addr));
}
__device__ __forceinline__ void mma_bf16(float* c, const uint32_t* a,
                                         uint32_t b0, uint32_t b1) {
    asm volatile(
        "mma.sync.aligned.m16n8k16.row.col.f32.bf16.bf16.f32 "
        "{%0,%1,%2,%3}, {%4,%5,%6,%7}, {%8,%9}, {%0,%1,%2,%3};\n"
        : "+f"(c[0]), "+f"(c[1]), "+f"(c[2]), "+f"(c[3])
        : "r"(a[0]), "r"(a[1]), "r"(a[2]), "r"(a[3]), "r"(b0), "r"(b1));
}
__device__ __forceinline__ void cp16(void* dst, const void* src) {
    uint32_t d = (uint32_t)__cvta_generic_to_shared(dst);
    asm volatile("cp.async.cg.shared.global [%0], [%1], 16;\n" :: "r"(d), "l"(src));
}

template <int BM, int BN, int WARPS_M, int WARPS_N, int WM>
__global__ __launch_bounds__(256, 2)
void gemm_mma_kernel(const __nv_bfloat16* __restrict__ Ahg,
                     const __nv_bfloat16* __restrict__ Alg,
                     const __nv_bfloat16* __restrict__ Bhg,
                     const __nv_bfloat16* __restrict__ Blg,
                     __half* __restrict__ Cf,
                     const float* __restrict__ a_src, const float* __restrict__ a_dst,
                     float* __restrict__ s, float* __restrict__ d,
                     float* __restrict__ smax,
                     int M, int K, int N, int H) {
    constexpr int BK = 32;
    constexpr int AP = 40;                 // 80B row stride
    constexpr int BP = BN + 8;
    constexpr int ASZ = BM * AP;
    constexpr int BSZ = BK * BP;
    constexpr int STAGE = 2 * ASZ + 2 * BSZ;
    extern __shared__ __align__(16) __nv_bfloat16 smem[];

    int tid = threadIdx.x, lane = tid & 31, warp = tid >> 5;
    int wm = warp % WARPS_M, wn = warp / WARPS_M;
    int wrow = wm * (WM * 16);
    int wcol = wn * 32;
    int m0 = blockIdx.x * BM, n0 = blockIdx.y * BN;

    float c[WM][4][4] = {};

    auto load = [&](int st, int k0) {
        __nv_bfloat16* sAh = smem + st * STAGE;
        __nv_bfloat16* sAl = sAh + ASZ;
        __nv_bfloat16* sBh = sAl + ASZ;
        __nv_bfloat16* sBl = sBh + BSZ;
        #pragma unroll
        for (int v = tid; v < BM * 4; v += 256) {
            int row = v >> 2, ch = (v & 3) * 8;
            int gm = m0 + row; if (gm >= M) gm = M - 1;  // clamp; stores guarded
            cp16(sAh + row * AP + ch, Ahg + (size_t)gm * K + k0 + ch);
            cp16(sAl + row * AP + ch, Alg + (size_t)gm * K + k0 + ch);
        }
        constexpr int BCH = BN / 8;
        #pragma unroll
        for (int v = tid; v < BK * BCH; v += 256) {
            int row = v / BCH, ch = (v % BCH) * 8;
            cp16(sBh + row * BP + ch, Bhg + (size_t)(k0 + row) * N + n0 + ch);
            cp16(sBl + row * BP + ch, Blg + (size_t)(k0 + row) * N + n0 + ch);
        }
        asm volatile("cp.async.commit_group;\n");
    };

    load(0, 0);
    int nT = K / BK;
    for (int t = 0; t < nT; ++t) {
        int st = t & 1;
        if (t + 1 < nT) {
            load(st ^ 1, (t + 1) * BK);
            asm volatile("cp.async.wait_group 1;\n");
        } else {
            asm volatile("cp.async.wait_group 0;\n");
        }
        __syncthreads();

        const __nv_bfloat16* sAh = smem + st * STAGE;
        const __nv_bfloat16* sAl = sAh + ASZ;
        const __nv_bfloat16* sBh = sAl + ASZ;
        const __nv_bfloat16* sBl = sBh + BSZ;

        #pragma unroll
        for (int kkh = 0; kkh < 2; ++kkh) {
            int kk = kkh * 16;
            uint32_t ah[WM][4], al[WM][4], bh[2][4], bl[2][4];
            #pragma unroll
            for (int im = 0; im < WM; ++im) {
                int r = wrow + im * 16 + (lane & 15);
                ldsm_x4(ah[im][0], ah[im][1], ah[im][2], ah[im][3],
                    (uint32_t)__cvta_generic_to_shared(
                        sAh + r * AP + kk + (lane >> 4) * 8));
                ldsm_x4(al[im][0], al[im][1], al[im][2], al[im][3],
                    (uint32_t)__cvta_generic_to_shared(
                        sAl + r * AP + kk + (lane >> 4) * 8));
            }
            #pragma unroll
            for (int jn = 0; jn < 2; ++jn) {
                int r = kk + (lane & 15);
                int cc = wcol + jn * 16 + (lane >> 4) * 8;
                ldsm_x4_t(bh[jn][0], bh[jn][1], bh[jn][2], bh[jn][3],
                    (uint32_t)__cvta_generic_to_shared(sBh + r * BP + cc));
                ldsm_x4_t(bl[jn][0], bl[jn][1], bl[jn][2], bl[jn][3],
                    (uint32_t)__cvta_generic_to_shared(sBl + r * BP + cc));
            }
            #pragma unroll
            for (int im = 0; im < WM; ++im) {
                #pragma unroll
                for (int j = 0; j < 4; ++j) {
                    uint32_t b0h = bh[j >> 1][(j & 1) * 2];
                    uint32_t b1h = bh[j >> 1][(j & 1) * 2 + 1];
                    uint32_t b0l = bl[j >> 1][(j & 1) * 2];
                    uint32_t b1l = bl[j >> 1][(j & 1) * 2 + 1];
                    mma_bf16(c[im][j], ah[im], b0h, b1h);
                    mma_bf16(c[im][j], al[im], b0h, b1h);
                    mma_bf16(c[im][j], ah[im], b0l, b1l);
                }
            }
        }
        __syncthreads();
    }

    // --- epilogue: fp16 store ---
    #pragma unroll
    for (int im = 0; im < WM; ++im) {
        #pragma unroll
        for (int j = 0; j < 4; ++j) {
            int r = wrow + im * 16 + (lane >> 2);
            int col = n0 + wcol + j * 8 + (lane & 3) * 2;
            int gr = m0 + r;
            if (gr < M)
                *reinterpret_cast<__half2*>(&Cf[(size_t)gr * N + col]) =
                    __floats2half2_rn(c[im][j][0], c[im][j][1]);
            if (gr + 8 < M)
                *reinterpret_cast<__half2*>(&Cf[(size_t)(gr + 8) * N + col]) =
                    __floats2half2_rn(c[im][j][2], c[im][j][3]);
        }
    }

    // --- fused s/d dots + smax (warp tile == one head's 32 columns) ---
    int head = (n0 + wcol) >> 5;
    float asv[8], adv[8];
    #pragma unroll
    for (int j = 0; j < 4; ++j)
        #pragma unroll
        for (int q = 0; q < 2; ++q) {
            int cc = j * 8 + (lane & 3) * 2 + q;
            asv[j * 2 + q] = a_src[head * 32 + cc];
            adv[j * 2 + q] = a_dst[head * 32 + cc];
        }
    float wmax = -1e30f;
    #pragma unroll
    for (int im = 0; im < WM; ++im) {
        float s1 = 0.f, d1 = 0.f, s2 = 0.f, d2 = 0.f;
        #pragma unroll
        for (int j = 0; j < 4; ++j)
            #pragma unroll
            for (int q = 0; q < 2; ++q) {
                float av = asv[j * 2 + q], dv = adv[j * 2 + q];
                s1 = fmaf(c[im][j][q],     av, s1);
                d1 = fmaf(c[im][j][q],     dv, d1);
                s2 = fmaf(c[im][j][2 + q], av, s2);
                d2 = fmaf(c[im][j][2 + q], dv, d2);
            }
        #pragma unroll
        for (int off = 1; off <= 2; off <<= 1) {
            s1 += __shfl_xor_sync(0xFFFFFFFFu, s1, off);
            d1 += __shfl_xor_sync(0xFFFFFFFFu, d1, off);
            s2 += __shfl_xor_sync(0xFFFFFFFFu, s2, off);
            d2 += __shfl_xor_sync(0xFFFFFFFFu, d2, off);
        }
        int r1 = m0 + wrow + im * 16 + (lane >> 2);
        if ((lane & 3) == 0) {
            if (r1 < M) {
                s[(size_t)r1 * H + head] = s1;
                d[(size_t)r1 * H + head] = d1;
                wmax = fmaxf(wmax, s1);
            }
            if (r1 + 8 < M) {
                s[(size_t)(r1 + 8) * H + head] = s2;
                d[(size_t)(r1 + 8) * H + head] = d2;
                wmax = fmaxf(wmax, s2);
            }
        }
    }
    #pragma unroll
    for (int off = 16; off > 0; off >>= 1)
        wmax = fmaxf(wmax, __shfl_xor_sync(0xFFFFFFFFu, wmax, off));
    if (lane == 0) atomicMaxFloat(&smax[head], wmax);
}

// ---------------------------------------------------------------------------
// Aggregation: one warp per (node, head-group of HG heads); H/HG warps per
// node. Fixed softmax shift m_h = leaky(smax_h + d_n,h). All h reads fp16.
// ---------------------------------------------------------------------------
template <int H, int HG, int ACT>
__global__ void agg_kernel(const __half* __restrict__ hf,
                           const float* __restrict__ s,
                           const float* __restrict__ d, const float* __restrict__ smax,
                           const float* __restrict__ bias,
                           float* __restrict__ outf, __nv_bfloat16* __restrict__ outh,
                           __nv_bfloat16* __restrict__ outl, int N) {
    constexpr int HC = H * 32;
    constexpr int WPN = H / HG;             // warps per node
    constexpr int EC = 32 / HG;             // edge slots per chunk
    int w = blockIdx.x * 8 + (threadIdx.x >> 5);
    int lane = threadIdx.x & 31;
    int n = w / WPN;
    int hg = w - n * WPN;
    if (n >= N) return;
    int hb = hg * HG;                       // first head of this group
    int eidx = lane / HG;
    int hidx = lane % HG;
    int head = hb + hidx;

    float dnh = d[(size_t)n * H + head];
    float mh = smax[head] + dnh;
    mh = (mh > 0.f) ? mh : 0.2f * mh;

    float den[HG], acc[HG];
    #pragma unroll
    for (int k = 0; k < HG; ++k) {
        float mk = __shfl_sync(0xFFFFFFFFu, mh, k);    // lane k: hidx==k
        float e0 = s[(size_t)n * H + hb + k] + d[(size_t)n * H + hb + k];
        e0 = (e0 > 0.f) ? e0 : 0.2f * e0;
        float w0 = __expf(e0 - mk);
        den[k] = w0;
        acc[k] = w0 * __half2float(hf[(size_t)n * HC + (hb + k) * 32 + lane]);
    }

    float edgeden = 0.f;
    int r0 = g_rowptr[n], r1 = g_rowptr[n + 1];
    for (int base = r0; base < r1; base += EC) {
        int cnt = r1 - base; if (cnt > EC) cnt = EC;
        int src = 0; float wgt = 0.f;
        if (eidx < cnt) {
            src = g_col[base + eidx];
            float e = s[(size_t)src * H + head] + dnh;
            e = (e > 0.f) ? e : 0.2f * e;
            wgt = __expf(e - mh);
            edgeden += wgt;
        }
        #pragma unroll
        for (int j = 0; j < EC; ++j) {
            if (j >= cnt) break;
            int sj = __shfl_sync(0xFFFFFFFFu, src, j * HG);
            const __half* hp = hf + (size_t)sj * HC + hb * 32 + lane;
            #pragma unroll
            for (int k = 0; k < HG; ++k) {
                float wk = __shfl_sync(0xFFFFFFFFu, wgt, j * HG + k);
                acc[k] = fmaf(wk, __half2float(hp[k * 32]), acc[k]);
            }
        }
    }
    #pragma unroll
    for (int off = HG; off < 32; off <<= 1)
        edgeden += __shfl_xor_sync(0xFFFFFFFFu, edgeden, off);
    #pragma unroll
    for (int k = 0; k < HG; ++k)
        den[k] += __shfl_sync(0xFFFFFFFFu, edgeden, k);

    if (ACT == 0) {
        #pragma unroll
        for (int k = 0; k < HG; ++k) {
            float o = acc[k] / den[k] + bias[(hb + k) * 32 + lane];
            o = (o > 0.f) ? o : expm1f(o);                  // ELU
            size_t idx = (size_t)n * HC + (hb + k) * 32 + lane;
            __nv_bfloat16 oh = __float2bfloat16(o);
            outh[idx] = oh;
            outl[idx] = __float2bfloat16(o - __bfloat162float(oh));
        }
    } else {
        float o = acc[0] / den[0] + bias[lane];
        float mx = o;
        #pragma unroll
        for (int off = 16; off > 0; off >>= 1)
            mx = fmaxf(mx, __shfl_xor_sync(0xFFFFFFFFu, mx, off));
        float ex = __expf(o - mx);
        float sum = ex;
        #pragma unroll
        for (int off = 16; off > 0; off >>= 1)
            sum += __shfl_xor_sync(0xFFFFFFFFu, sum, off);
        outf[(size_t)n * 32 + lane] = o - mx - logf(sum);
    }
}

// ---------------------------------------------------------------------------
// Launch. CSR build runs on a second stream, overlapped with prep + gemm1.
// Streams/events are created once on the first (uncaptured) call; the
// fork/join via events is graph-capturable.
// ---------------------------------------------------------------------------
extern "C" void kernel_launch(void* const* d_in, const int* in_sizes, int n_in,
                              void* d_out, int out_size) {
    const float* x  = (const float*)d_in[0];
    const void*  ei = d_in[1];
    const float* W[4]    = {(const float*)d_in[2],  (const float*)d_in[6],
                            (const float*)d_in[10], (const float*)d_in[14]};
    const float* asrc[4] = {(const float*)d_in[3],  (const float*)d_in[7],
                            (const float*)d_in[11], (const float*)d_in[15]};
    const float* adst[4] = {(const float*)d_in[4],  (const float*)d_in[8],
                            (const float*)d_in[12], (const float*)d_in[16]};
    const float* bs[4]   = {(const float*)d_in[5],  (const float*)d_in[9],
                            (const float*)d_in[13], (const float*)d_in[17]};

    int N = in_sizes[0] / 256;
    int E = in_sizes[1] / 2;

    float *sb, *db, *smaxb;
    __half *hf;
    __nv_bfloat16 *ah, *al, *wh, *wl;
    cudaGetSymbolAddress((void**)&hf,    g_hf);
    cudaGetSymbolAddress((void**)&sb,    g_s);
    cudaGetSymbolAddress((void**)&db,    g_d);
    cudaGetSymbolAddress((void**)&smaxb, g_smax);
    cudaGetSymbolAddress((void**)&ah,    g_ah);
    cudaGetSymbolAddress((void**)&al,    g_al);
    cudaGetSymbolAddress((void**)&wh,    g_wh);
    cudaGetSymbolAddress((void**)&wl,    g_wl);

    static cudaStream_t s2 = nullptr;
    static cudaEvent_t evFork = nullptr, evJoin = nullptr;
    if (!s2) {
        cudaStreamCreateWithFlags(&s2, cudaStreamNonBlocking);
        cudaEventCreateWithFlags(&evFork, cudaEventDisableTiming);
        cudaEventCreateWithFlags(&evJoin, cudaEventDisableTiming);
    }

    const int Hs[4]   = {8, 4, 2, 1};
    const int Ks[4]   = {256, 256, 128, 64};
    const int HCs[4]  = {256, 128, 64, 32};
    const int woff[4] = {0, 65536, 98304, 106496};

    const int SM1 = (2 * 96 * 40 + 2 * 32 * 136) * 2 * 2;    // 65536
    const int SM3 = (2 * 128 * 40 + 2 * 32 * 72) * 2 * 2;    // 59392
    const int SM4 = (2 * 128 * 40 + 2 * 32 * 40) * 2 * 2;    // 51200
    cudaFuncSetAttribute(gemm_mma_kernel<96, 128, 2, 4, 3>,
                         cudaFuncAttributeMaxDynamicSharedMemorySize, SM1);
    cudaFuncSetAttribute(gemm_mma_kernel<128, 64, 4, 2, 2>,
                         cudaFuncAttributeMaxDynamicSharedMemorySize, SM3);
    cudaFuncSetAttribute(gemm_mma_kernel<128, 32, 8, 1, 1>,
                         cudaFuncAttributeMaxDynamicSharedMemorySize, SM4);

    int gx96 = (N + 95) / 96;
    int gx128 = (N + 127) / 128;
    int nb = (N + 511) / 512;

    PrepArgs pa;
    pa.src[0] = x;    pa.oh[0] = ah; pa.ol[0] = al;
    int acc4 = N * 256 / 4;
    pa.start4[0] = 0;
    for (int L = 0; L < 4; ++L) {
        pa.src[L + 1] = W[L];
        pa.oh[L + 1] = wh + woff[L];
        pa.ol[L + 1] = wl + woff[L];
        pa.start4[L + 1] = acc4;
        acc4 += Ks[L] * HCs[L] / 4;
    }
    pa.total4 = acc4;

    // Fork: CSR chain on s2, concurrent with prep + gemm1 on the main stream.
    cudaEventRecord(evFork, 0);
    cudaStreamWaitEvent(s2, evFork, 0);

    prep_kernel<<<(pa.total4 + 255) / 256, 256>>>(pa);                    // 0
    detzero_kernel<<<(N + 255) / 256, 256, 0, s2>>>((const int*)ei, E, N);// 1
    hist_kernel<<<(E + 255) / 256, 256, 0, s2>>>(ei, E);                  // 2
    gemm_mma_kernel<96, 128, 2, 4, 3><<<dim3(gx96, 2), 256, SM1>>>(       // 3
        ah, al, wh, wl, hf, asrc[0], adst[0], sb, db, smaxb, N, 256, 256, 8);
    scan1_kernel<<<nb, 512, 0, s2>>>(N);
    scan2_kernel<<<1, 128, 0, s2>>>(nb, N);
    scan3_kernel<<<nb, 512, 0, s2>>>(N);
    scatter_kernel<<<(E + 255) / 256, 256, 0, s2>>>(ei, E);
    cudaEventRecord(evJoin, s2);
    cudaStreamWaitEvent(0, evJoin, 0);

    // --- layer 1 aggregation: 2 warps/node (HG=4) ---
    agg_kernel<8, 4, 0><<<(N * 2 + 7) / 8, 256>>>(hf, sb, db, smaxb, bs[0],
                                                  nullptr, ah, al, N);

    // --- layers 2-4 ---
    for (int L = 1; L < 4; ++L) {
        int K = Ks[L], HC = HCs[L], H = Hs[L];
        const __nv_bfloat16* whl = wh + woff[L];
        const __nv_bfloat16* wll = wl + woff[L];
        float* smL = smaxb + L * 8;
        if (L == 1)
            gemm_mma_kernel<96, 128, 2, 4, 3><<<dim3(gx96, 1), 256, SM1>>>(
                ah, al, whl, wll, hf, asrc[L], adst[L], sb, db, smL, N, K, HC, H);
        else if (L == 2)
            gemm_mma_kernel<128, 64, 4, 2, 2><<<dim3(gx128, 1), 256, SM3>>>(
                ah, al, whl, wll, hf, asrc[L], adst[L], sb, db, smL, N, K, HC, H);
        else
            gemm_mma_kernel<128, 32, 8, 1, 1><<<dim3(gx128, 1), 256, SM4>>>(
                ah, al, whl, wll, hf, asrc[L], adst[L], sb, db, smL, N, K, HC, H);

        switch (H) {
            case 4:   // 2 warps/node (HG=2)
                agg_kernel<4, 2, 0><<<(N * 2 + 7) / 8, 256>>>(hf, sb, db, smL, bs[L],
                                                              nullptr, ah, al, N);
                break;
            case 2:   // 2 warps/node (HG=1)
                agg_kernel<2, 1, 0><<<(N * 2 + 7) / 8, 256>>>(hf, sb, db, smL, bs[L],
                                                              nullptr, ah, al, N);
                break;
            default:  // H=1
                agg_kernel<1, 1, 1><<<(N + 7) / 8, 256>>>(hf, sb, db, smL, bs[L],
                                                          (float*)d_out, nullptr,
                                                          nullptr, N);
                break;
        }
    }
}

// round 14
// speedup vs baseline: 1.0397x; 1.0397x over previous
#include <cuda_runtime.h>
#include <cuda_bf16.h>
#include <cuda_fp16.h>
#include <math.h>
#include <stdint.h>

// ---------------------------------------------------------------------------
// GAT, 4 layers. N=50000, E=400000, F=256.
// Layers: 256->8x32, 256->4x32, 128->2x32, 64->1x32 (+ final log_softmax).
// ---------------------------------------------------------------------------
#define MAXN 50000
#define MAXE 400000

__device__ __half g_hf[MAXN * 256];            // h fp16 (agg gathers + self)
__device__ __nv_bfloat16 g_ah[MAXN * 256];     // layer input, bf16 high
__device__ __nv_bfloat16 g_al[MAXN * 256];     // layer input, bf16 low
__device__ __nv_bfloat16 g_wh[108544];         // all 4 W's, bf16 high
__device__ __nv_bfloat16 g_wl[108544];         // all 4 W's, bf16 low
__device__ float g_s[MAXN * 8];
__device__ float g_d[MAXN * 8];
__device__ float g_smax[32];                   // 4 layers x 8 heads
__device__ int   g_deg[MAXN];
__device__ int   g_rowptr[MAXN + 1];
__device__ int   g_cur[MAXN];
__device__ int   g_col[MAXE];
__device__ int   g_bsum[1024];
__device__ int   g_boff[1024];
__device__ int   g_is64;

// ---------------------------------------------------------------------------
// prep: all fp32 -> bf16(h,l) splits in one kernel + smax init
// ---------------------------------------------------------------------------
struct PrepArgs {
    const float* src[5];
    __nv_bfloat16* oh[5];
    __nv_bfloat16* ol[5];
    int start4[5];
    int total4;
};

__global__ void prep_kernel(PrepArgs a) {
    if (blockIdx.x == 0 && threadIdx.x < 32) g_smax[threadIdx.x] = -1e30f;
    int i = blockIdx.x * 256 + threadIdx.x;
    if (i >= a.total4) return;
    int seg = 0;
    #pragma unroll
    for (int k = 1; k < 5; ++k) if (i >= a.start4[k]) seg = k;
    int j = i - a.start4[seg];
    float4 f = reinterpret_cast<const float4*>(a.src[seg])[j];
    __nv_bfloat16 h0 = __float2bfloat16(f.x), h1 = __float2bfloat16(f.y);
    __nv_bfloat16 h2 = __float2bfloat16(f.z), h3 = __float2bfloat16(f.w);
    reinterpret_cast<__nv_bfloat162*>(a.oh[seg])[2 * j]     = __nv_bfloat162(h0, h1);
    reinterpret_cast<__nv_bfloat162*>(a.oh[seg])[2 * j + 1] = __nv_bfloat162(h2, h3);
    reinterpret_cast<__nv_bfloat162*>(a.ol[seg])[2 * j] = __nv_bfloat162(
        __float2bfloat16(f.x - __bfloat162float(h0)),
        __float2bfloat16(f.y - __bfloat162float(h1)));
    reinterpret_cast<__nv_bfloat162*>(a.ol[seg])[2 * j + 1] = __nv_bfloat162(
        __float2bfloat16(f.z - __bfloat162float(h2)),
        __float2bfloat16(f.w - __bfloat162float(h3)));
}

// ---------------------------------------------------------------------------
// CSR build (by dst)
// ---------------------------------------------------------------------------
__global__ void detzero_kernel(const int* __restrict__ ei32, int E, int N) {
    int i = blockIdx.x * blockDim.x + threadIdx.x;
    if (i < N) g_deg[i] = 0;
    if (blockIdx.x == 0 && threadIdx.x == 0) {
        int all_zero = 1;
        for (int k = 1; k < 64 && k < 2 * E; k += 2)
            if (ei32[k] != 0) { all_zero = 0; break; }
        g_is64 = all_zero;
    }
}

__device__ __forceinline__ int edge_val(const void* ei, int E, int which, int e) {
    if (g_is64) {
        const long long* p = (const long long*)ei;
        return (int)p[(size_t)which * E + e];
    } else {
        const int* p = (const int*)ei;
        return p[(size_t)which * E + e];
    }
}

__global__ void hist_kernel(const void* __restrict__ ei, int E) {
    int e = blockIdx.x * blockDim.x + threadIdx.x;
    if (e < E) atomicAdd(&g_deg[edge_val(ei, E, 1, e)], 1);
}

__global__ void scan1_kernel(int N) {
    __shared__ int ws[16];
    int tid = threadIdx.x;                 // 512 threads
    int lane = tid & 31, warp = tid >> 5;
    int i = blockIdx.x * 512 + tid;
    int v = (i < N) ? g_deg[i] : 0;
    int x = v;
    #pragma unroll
    for (int off = 1; off < 32; off <<= 1) {
        int y = __shfl_up_sync(0xFFFFFFFFu, x, off);
        if (lane >= off) x += y;
    }
    if (lane == 31) ws[warp] = x;
    __syncthreads();
    if (tid < 16) {
        int y = ws[tid];
        #pragma unroll
        for (int off = 1; off < 16; off <<= 1) {
            int z = __shfl_up_sync(0x0000FFFFu, y, off);
            if (tid >= off) y += z;
        }
        ws[tid] = y;
    }
    __syncthreads();
    int woff = (warp > 0) ? ws[warp - 1] : 0;
    if (i < N) g_rowptr[i] = x - v + woff;
    if (tid == 0) g_bsum[blockIdx.x] = ws[15];
}

__global__ void scan2_kernel(int nb, int N) {
    __shared__ int ws[4];
    int tid = threadIdx.x;                 // 128 threads, nb <= 128
    int lane = tid & 31, warp = tid >> 5;
    int v = (tid < nb) ? g_bsum[tid] : 0;
    int x = v;
    #pragma unroll
    for (int off = 1; off < 32; off <<= 1) {
        int y = __shfl_up_sync(0xFFFFFFFFu, x, off);
        if (lane >= off) x += y;
    }
    if (lane == 31) ws[warp] = x;
    __syncthreads();
    if (tid < 4) {
        int y = ws[tid];
        #pragma unroll
        for (int off = 1; off < 4; off <<= 1) {
            int z = __shfl_up_sync(0x0000000Fu, y, off);
            if (tid >= off) y += z;
        }
        ws[tid] = y;
    }
    __syncthreads();
    int woff = (warp > 0) ? ws[warp - 1] : 0;
    g_boff[tid] = x - v + woff;
    if (tid == 127) g_rowptr[N] = x + woff;
}

__global__ void scan3_kernel(int N) {
    int i = blockIdx.x * 512 + threadIdx.x;
    if (i < N) {
        int val = g_rowptr[i] + g_boff[blockIdx.x];
        g_rowptr[i] = val;
        g_cur[i] = val;
    }
}

__global__ void scatter_kernel(const void* __restrict__ ei, int E) {
    int e = blockIdx.x * blockDim.x + threadIdx.x;
    if (e < E) {
        int d = edge_val(ei, E, 1, e);
        int s = edge_val(ei, E, 0, e);
        g_col[atomicAdd(&g_cur[d], 1)] = s;
    }
}

__device__ __forceinline__ void atomicMaxFloat(float* addr, float val) {
    if (val >= 0.f) atomicMax((int*)addr, __float_as_int(val));
    else atomicMin((unsigned int*)addr, __float_as_uint(val));
}

// ---------------------------------------------------------------------------
// Tensor-core GEMM: BK=32, 2-stage cp.async, dynamic smem, fused sd/smax
// epilogue, fp16 output. C = Ah*Bh + Al*Bh + Ah*Bl (fp32 accum).
// ---------------------------------------------------------------------------
__device__ __forceinline__ void ldsm_x4(uint32_t& r0, uint32_t& r1, uint32_t& r2,
                                        uint32_t& r3, uint32_t addr) {
    asm volatile("ldmatrix.sync.aligned.m8n8.x4.shared.b16 {%0,%1,%2,%3}, [%4];\n"
                 : "=r"(r0), "=r"(r1), "=r"(r2), "=r"(r3) : "r"(addr));
}
__device__ __forceinline__ void ldsm_x4_t(uint32_t& r0, uint32_t& r1, uint32_t& r2,
                                          uint32_t& r3, uint32_t addr) {
    asm volatile("ldmatrix.sync.aligned.m8n8.x4.trans.shared.b16 {%0,%1,%2,%3}, [%4];\n"
                 : "=r"(r0), "=r"(r1), "=r"(r2), "=r"(r3) : "r"(addr));
}
__device__ __forceinline__ void mma_bf16(float* c, const uint32_t* a,
                                         uint32_t b0, uint32_t b1) {
    asm volatile(
        "mma.sync.aligned.m16n8k16.row.col.f32.bf16.bf16.f32 "
        "{%0,%1,%2,%3}, {%4,%5,%6,%7}, {%8,%9}, {%0,%1,%2,%3};\n"
        : "+f"(c[0]), "+f"(c[1]), "+f"(c[2]), "+f"(c[3])
        : "r"(a[0]), "r"(a[1]), "r"(a[2]), "r"(a[3]), "r"(b0), "r"(b1));
}
__device__ __forceinline__ void cp16(void* dst, const void* src) {
    uint32_t d = (uint32_t)__cvta_generic_to_shared(dst);
    asm volatile("cp.async.cg.shared.global [%0], [%1], 16;\n" :: "r"(d), "l"(src));
}

template <int BM, int BN, int WARPS_M, int WARPS_N, int WM>
__global__ __launch_bounds__(256, 2)
void gemm_mma_kernel(const __nv_bfloat16* __restrict__ Ahg,
                     const __nv_bfloat16* __restrict__ Alg,
                     const __nv_bfloat16* __restrict__ Bhg,
                     const __nv_bfloat16* __restrict__ Blg,
                     __half* __restrict__ Cf,
                     const float* __restrict__ a_src, const float* __restrict__ a_dst,
                     float* __restrict__ s, float* __restrict__ d,
                     float* __restrict__ smax,
                     int M, int K, int N, int H) {
    constexpr int BK = 32;
    constexpr int AP = 40;                 // 80B row stride
    constexpr int BP = BN + 8;
    constexpr int ASZ = BM * AP;
    constexpr int BSZ = BK * BP;
    constexpr int STAGE = 2 * ASZ + 2 * BSZ;
    extern __shared__ __align__(16) __nv_bfloat16 smem[];

    int tid = threadIdx.x, lane = tid & 31, warp = tid >> 5;
    int wm = warp % WARPS_M, wn = warp / WARPS_M;
    int wrow = wm * (WM * 16);
    int wcol = wn * 32;
    int m0 = blockIdx.x * BM, n0 = blockIdx.y * BN;

    float c[WM][4][4] = {};

    auto load = [&](int st, int k0) {
        __nv_bfloat16* sAh = smem + st * STAGE;
        __nv_bfloat16* sAl = sAh + ASZ;
        __nv_bfloat16* sBh = sAl + ASZ;
        __nv_bfloat16* sBl = sBh + BSZ;
        #pragma unroll
        for (int v = tid; v < BM * 4; v += 256) {
            int row = v >> 2, ch = (v & 3) * 8;
            int gm = m0 + row; if (gm >= M) gm = M - 1;  // clamp; stores guarded
            cp16(sAh + row * AP + ch, Ahg + (size_t)gm * K + k0 + ch);
            cp16(sAl + row * AP + ch, Alg + (size_t)gm * K + k0 + ch);
        }
        constexpr int BCH = BN / 8;
        #pragma unroll
        for (int v = tid; v < BK * BCH; v += 256) {
            int row = v / BCH, ch = (v % BCH) * 8;
            cp16(sBh + row * BP + ch, Bhg + (size_t)(k0 + row) * N + n0 + ch);
            cp16(sBl + row * BP + ch, Blg + (size_t)(k0 + row) * N + n0 + ch);
        }
        asm volatile("cp.async.commit_group;\n");
    };

    load(0, 0);
    int nT = K / BK;
    for (int t = 0; t < nT; ++t) {
        int st = t & 1;
        if (t + 1 < nT) {
            load(st ^ 1, (t + 1) * BK);
            asm volatile("cp.async.wait_group 1;\n");
        } else {
            asm volatile("cp.async.wait_group 0;\n");
        }
        __syncthreads();

        const __nv_bfloat16* sAh = smem + st * STAGE;
        const __nv_bfloat16* sAl = sAh + ASZ;
        const __nv_bfloat16* sBh = sAl + ASZ;
        const __nv_bfloat16* sBl = sBh + BSZ;

        #pragma unroll
        for (int kkh = 0; kkh < 2; ++kkh) {
            int kk = kkh * 16;
            uint32_t ah[WM][4], al[WM][4], bh[2][4], bl[2][4];
            #pragma unroll
            for (int im = 0; im < WM; ++im) {
                int r = wrow + im * 16 + (lane & 15);
                ldsm_x4(ah[im][0], ah[im][1], ah[im][2], ah[im][3],
                    (uint32_t)__cvta_generic_to_shared(
                        sAh + r * AP + kk + (lane >> 4) * 8));
                ldsm_x4(al[im][0], al[im][1], al[im][2], al[im][3],
                    (uint32_t)__cvta_generic_to_shared(
                        sAl + r * AP + kk + (lane >> 4) * 8));
            }
            #pragma unroll
            for (int jn = 0; jn < 2; ++jn) {
                int r = kk + (lane & 15);
                int cc = wcol + jn * 16 + (lane >> 4) * 8;
                ldsm_x4_t(bh[jn][0], bh[jn][1], bh[jn][2], bh[jn][3],
                    (uint32_t)__cvta_generic_to_shared(sBh + r * BP + cc));
                ldsm_x4_t(bl[jn][0], bl[jn][1], bl[jn][2], bl[jn][3],
                    (uint32_t)__cvta_generic_to_shared(sBl + r * BP + cc));
            }
            #pragma unroll
            for (int im = 0; im < WM; ++im) {
                #pragma unroll
                for (int j = 0; j < 4; ++j) {
                    uint32_t b0h = bh[j >> 1][(j & 1) * 2];
                    uint32_t b1h = bh[j >> 1][(j & 1) * 2 + 1];
                    uint32_t b0l = bl[j >> 1][(j & 1) * 2];
                    uint32_t b1l = bl[j >> 1][(j & 1) * 2 + 1];
                    mma_bf16(c[im][j], ah[im], b0h, b1h);
                    mma_bf16(c[im][j], al[im], b0h, b1h);
                    mma_bf16(c[im][j], ah[im], b0l, b1l);
                }
            }
        }
        __syncthreads();
    }

    // --- epilogue: fp16 store ---
    #pragma unroll
    for (int im = 0; im < WM; ++im) {
        #pragma unroll
        for (int j = 0; j < 4; ++j) {
            int r = wrow + im * 16 + (lane >> 2);
            int col = n0 + wcol + j * 8 + (lane & 3) * 2;
            int gr = m0 + r;
            if (gr < M)
                *reinterpret_cast<__half2*>(&Cf[(size_t)gr * N + col]) =
                    __floats2half2_rn(c[im][j][0], c[im][j][1]);
            if (gr + 8 < M)
                *reinterpret_cast<__half2*>(&Cf[(size_t)(gr + 8) * N + col]) =
                    __floats2half2_rn(c[im][j][2], c[im][j][3]);
        }
    }

    // --- fused s/d dots + smax (warp tile == one head's 32 columns) ---
    int head = (n0 + wcol) >> 5;
    float asv[8], adv[8];
    #pragma unroll
    for (int j = 0; j < 4; ++j)
        #pragma unroll
        for (int q = 0; q < 2; ++q) {
            int cc = j * 8 + (lane & 3) * 2 + q;
            asv[j * 2 + q] = a_src[head * 32 + cc];
            adv[j * 2 + q] = a_dst[head * 32 + cc];
        }
    float wmax = -1e30f;
    #pragma unroll
    for (int im = 0; im < WM; ++im) {
        float s1 = 0.f, d1 = 0.f, s2 = 0.f, d2 = 0.f;
        #pragma unroll
        for (int j = 0; j < 4; ++j)
            #pragma unroll
            for (int q = 0; q < 2; ++q) {
                float av = asv[j * 2 + q], dv = adv[j * 2 + q];
                s1 = fmaf(c[im][j][q],     av, s1);
                d1 = fmaf(c[im][j][q],     dv, d1);
                s2 = fmaf(c[im][j][2 + q], av, s2);
                d2 = fmaf(c[im][j][2 + q], dv, d2);
            }
        #pragma unroll
        for (int off = 1; off <= 2; off <<= 1) {
            s1 += __shfl_xor_sync(0xFFFFFFFFu, s1, off);
            d1 += __shfl_xor_sync(0xFFFFFFFFu, d1, off);
            s2 += __shfl_xor_sync(0xFFFFFFFFu, s2, off);
            d2 += __shfl_xor_sync(0xFFFFFFFFu, d2, off);
        }
        int r1 = m0 + wrow + im * 16 + (lane >> 2);
        if ((lane & 3) == 0) {
            if (r1 < M) {
                s[(size_t)r1 * H + head] = s1;
                d[(size_t)r1 * H + head] = d1;
                wmax = fmaxf(wmax, s1);
            }
            if (r1 + 8 < M) {
                s[(size_t)(r1 + 8) * H + head] = s2;
                d[(size_t)(r1 + 8) * H + head] = d2;
                wmax = fmaxf(wmax, s2);
            }
        }
    }
    #pragma unroll
    for (int off = 16; off > 0; off >>= 1)
        wmax = fmaxf(wmax, __shfl_xor_sync(0xFFFFFFFFu, wmax, off));
    if (lane == 0) atomicMaxFloat(&smax[head], wmax);
}

// ---------------------------------------------------------------------------
// Aggregation: one warp per NODE. Fixed softmax shift
// m_h = leaky(smax_h + d_n,h) >= every edge score (leaky monotone).
// Gather phase is half2-vectorized: lanes (c2 = lane&15, slot = lane>>4)
// load channel-pair c2 of head k for edges 2i+slot -> half the gather
// instructions and shuffles vs scalar, same sector traffic. Self-loop added
// after the slot reduction.
// ---------------------------------------------------------------------------
template <int H, int ACT>
__global__ void agg_kernel(const __half* __restrict__ hf,
                           const float* __restrict__ s,
                           const float* __restrict__ d, const float* __restrict__ smax,
                           const float* __restrict__ bias,
                           float* __restrict__ outf, __nv_bfloat16* __restrict__ outh,
                           __nv_bfloat16* __restrict__ outl, int N) {
    constexpr int HC = H * 32;
    constexpr int EC = 32 / H;              // edges per chunk
    int n = blockIdx.x * 8 + (threadIdx.x >> 5);
    int lane = threadIdx.x & 31;
    if (n >= N) return;
    int eidx = lane / H;
    int hidx = lane % H;
    int c2 = lane & 15;
    int slot = lane >> 4;
    const __half2* hf2 = reinterpret_cast<const __half2*>(hf);

    float dnh = d[(size_t)n * H + hidx];
    float mh = smax[hidx] + dnh;
    mh = (mh > 0.f) ? mh : 0.2f * mh;

    float den[H], w0[H];
    float2 acc2[H];
    #pragma unroll
    for (int k = 0; k < H; ++k) {
        float mk = __shfl_sync(0xFFFFFFFFu, mh, k);    // lane k holds head k
        float e0 = s[(size_t)n * H + k] + d[(size_t)n * H + k];
        e0 = (e0 > 0.f) ? e0 : 0.2f * e0;
        w0[k] = __expf(e0 - mk);
        den[k] = w0[k];
        acc2[k] = make_float2(0.f, 0.f);
    }

    float edgeden = 0.f;
    int r0 = g_rowptr[n], r1 = g_rowptr[n + 1];
    for (int base = r0; base < r1; base += EC) {
        int cnt = r1 - base; if (cnt > EC) cnt = EC;
        int src = 0; float w = 0.f;
        if (eidx < cnt) {
            src = g_col[base + eidx];
            float e = s[(size_t)src * H + hidx] + dnh;
            e = (e > 0.f) ? e : 0.2f * e;
            w = __expf(e - mh);
            edgeden += w;
        }
        // gather: lanes 0-15 take edge 2i, lanes 16-31 take edge 2i+1
        #pragma unroll
        for (int i = 0; i < EC / 2; ++i) {
            int j = 2 * i + slot;
            bool valid = j < cnt;
            int sj = __shfl_sync(0xFFFFFFFFu, src, j * H);
            size_t rowbase = (size_t)sj * (HC / 2) + c2;
            #pragma unroll
            for (int k = 0; k < H; ++k) {
                float wk = __shfl_sync(0xFFFFFFFFu, w, j * H + k);
                if (valid) {
                    float2 f = __half22float2(hf2[rowbase + k * 16]);
                    acc2[k].x = fmaf(wk, f.x, acc2[k].x);
                    acc2[k].y = fmaf(wk, f.y, acc2[k].y);
                }
            }
        }
    }
    // reduce per-lane edge denominators across edge slots (same head)
    #pragma unroll
    for (int off = H; off < 32; off <<= 1)
        edgeden += __shfl_xor_sync(0xFFFFFFFFu, edgeden, off);
    #pragma unroll
    for (int k = 0; k < H; ++k)
        den[k] += __shfl_sync(0xFFFFFFFFu, edgeden, k);
    // combine the two edge-slot halves, then add self contribution
    #pragma unroll
    for (int k = 0; k < H; ++k) {
        acc2[k].x += __shfl_xor_sync(0xFFFFFFFFu, acc2[k].x, 16);
        acc2[k].y += __shfl_xor_sync(0xFFFFFFFFu, acc2[k].y, 16);
        float2 f = __half22float2(hf2[(size_t)n * (HC / 2) + k * 16 + c2]);
        acc2[k].x = fmaf(w0[k], f.x, acc2[k].x);
        acc2[k].y = fmaf(w0[k], f.y, acc2[k].y);
    }

    if (ACT == 0) {
        if (slot == 0) {
            #pragma unroll
            for (int k = 0; k < H; ++k) {
                float ox = acc2[k].x / den[k] + bias[k * 32 + 2 * c2];
                float oy = acc2[k].y / den[k] + bias[k * 32 + 2 * c2 + 1];
                ox = (ox > 0.f) ? ox : expm1f(ox);          // ELU
                oy = (oy > 0.f) ? oy : expm1f(oy);
                size_t idx2 = ((size_t)n * HC + k * 32) / 2 + c2;
                __nv_bfloat16 hx = __float2bfloat16(ox);
                __nv_bfloat16 hy = __float2bfloat16(oy);
                reinterpret_cast<__nv_bfloat162*>(outh)[idx2] = __nv_bfloat162(hx, hy);
                reinterpret_cast<__nv_bfloat162*>(outl)[idx2] = __nv_bfloat162(
                    __float2bfloat16(ox - __bfloat162float(hx)),
                    __float2bfloat16(oy - __bfloat162float(hy)));
            }
        }
    } else {
        // H == 1: log_softmax over 32 classes, 2 per lane in lanes 0-15
        // (lanes 16-31 hold duplicates after the xor-16 reduce).
        float ox = acc2[0].x / den[0] + bias[2 * c2];
        float oy = acc2[0].y / den[0] + bias[2 * c2 + 1];
        float mx = fmaxf(ox, oy);
        #pragma unroll
        for (int off = 1; off < 16; off <<= 1)
            mx = fmaxf(mx, __shfl_xor_sync(0xFFFFFFFFu, mx, off));
        float sum = __expf(ox - mx) + __expf(oy - mx);
        #pragma unroll
        for (int off = 1; off < 16; off <<= 1)
            sum += __shfl_xor_sync(0xFFFFFFFFu, sum, off);
        if (slot == 0) {
            float lg = logf(sum);
            reinterpret_cast<float2*>(outf)[(size_t)n * 16 + c2] =
                make_float2(ox - mx - lg, oy - mx - lg);
        }
    }
}

// ---------------------------------------------------------------------------
// Launch (single stream — R13's fork/join regressed; reverted).
// ---------------------------------------------------------------------------
extern "C" void kernel_launch(void* const* d_in, const int* in_sizes, int n_in,
                              void* d_out, int out_size) {
    const float* x  = (const float*)d_in[0];
    const void*  ei = d_in[1];
    const float* W[4]    = {(const float*)d_in[2],  (const float*)d_in[6],
                            (const float*)d_in[10], (const float*)d_in[14]};
    const float* asrc[4] = {(const float*)d_in[3],  (const float*)d_in[7],
                            (const float*)d_in[11], (const float*)d_in[15]};
    const float* adst[4] = {(const float*)d_in[4],  (const float*)d_in[8],
                            (const float*)d_in[12], (const float*)d_in[16]};
    const float* bs[4]   = {(const float*)d_in[5],  (const float*)d_in[9],
                            (const float*)d_in[13], (const float*)d_in[17]};

    int N = in_sizes[0] / 256;
    int E = in_sizes[1] / 2;

    float *sb, *db, *smaxb;
    __half *hf;
    __nv_bfloat16 *ah, *al, *wh, *wl;
    cudaGetSymbolAddress((void**)&hf,    g_hf);
    cudaGetSymbolAddress((void**)&sb,    g_s);
    cudaGetSymbolAddress((void**)&db,    g_d);
    cudaGetSymbolAddress((void**)&smaxb, g_smax);
    cudaGetSymbolAddress((void**)&ah,    g_ah);
    cudaGetSymbolAddress((void**)&al,    g_al);
    cudaGetSymbolAddress((void**)&wh,    g_wh);
    cudaGetSymbolAddress((void**)&wl,    g_wl);

    const int Hs[4]   = {8, 4, 2, 1};
    const int Ks[4]   = {256, 256, 128, 64};
    const int HCs[4]  = {256, 128, 64, 32};
    const int woff[4] = {0, 65536, 98304, 106496};

    const int SM1 = (2 * 96 * 40 + 2 * 32 * 136) * 2 * 2;    // 65536
    const int SM3 = (2 * 128 * 40 + 2 * 32 * 72) * 2 * 2;    // 59392
    const int SM4 = (2 * 128 * 40 + 2 * 32 * 40) * 2 * 2;    // 51200
    cudaFuncSetAttribute(gemm_mma_kernel<96, 128, 2, 4, 3>,
                         cudaFuncAttributeMaxDynamicSharedMemorySize, SM1);
    cudaFuncSetAttribute(gemm_mma_kernel<128, 64, 4, 2, 2>,
                         cudaFuncAttributeMaxDynamicSharedMemorySize, SM3);
    cudaFuncSetAttribute(gemm_mma_kernel<128, 32, 8, 1, 1>,
                         cudaFuncAttributeMaxDynamicSharedMemorySize, SM4);

    int gx96 = (N + 95) / 96;
    int gx128 = (N + 127) / 128;
    int aggb = (N + 7) / 8;
    int nb = (N + 511) / 512;

    PrepArgs pa;
    pa.src[0] = x;    pa.oh[0] = ah; pa.ol[0] = al;
    int acc4 = N * 256 / 4;
    pa.start4[0] = 0;
    for (int L = 0; L < 4; ++L) {
        pa.src[L + 1] = W[L];
        pa.oh[L + 1] = wh + woff[L];
        pa.ol[L + 1] = wl + woff[L];
        pa.start4[L + 1] = acc4;
        acc4 += Ks[L] * HCs[L] / 4;
    }
    pa.total4 = acc4;

    prep_kernel<<<(pa.total4 + 255) / 256, 256>>>(pa);                    // 0
    detzero_kernel<<<(N + 255) / 256, 256>>>((const int*)ei, E, N);       // 1
    hist_kernel<<<(E + 255) / 256, 256>>>(ei, E);                         // 2
    gemm_mma_kernel<96, 128, 2, 4, 3><<<dim3(gx96, 2), 256, SM1>>>(       // 3
        ah, al, wh, wl, hf, asrc[0], adst[0], sb, db, smaxb, N, 256, 256, 8);
    scan1_kernel<<<nb, 512>>>(N);
    scan2_kernel<<<1, 128>>>(nb, N);
    scan3_kernel<<<nb, 512>>>(N);
    scatter_kernel<<<(E + 255) / 256, 256>>>(ei, E);

    // --- layer 1 aggregation ---
    agg_kernel<8, 0><<<aggb, 256>>>(hf, sb, db, smaxb, bs[0], nullptr, ah, al, N);

    // --- layers 2-4 ---
    for (int L = 1; L < 4; ++L) {
        int K = Ks[L], HC = HCs[L], H = Hs[L];
        const __nv_bfloat16* whl = wh + woff[L];
        const __nv_bfloat16* wll = wl + woff[L];
        float* smL = smaxb + L * 8;
        if (L == 1)
            gemm_mma_kernel<96, 128, 2, 4, 3><<<dim3(gx96, 1), 256, SM1>>>(
                ah, al, whl, wll, hf, asrc[L], adst[L], sb, db, smL, N, K, HC, H);
        else if (L == 2)
            gemm_mma_kernel<128, 64, 4, 2, 2><<<dim3(gx128, 1), 256, SM3>>>(
                ah, al, whl, wll, hf, asrc[L], adst[L], sb, db, smL, N, K, HC, H);
        else
            gemm_mma_kernel<128, 32, 8, 1, 1><<<dim3(gx128, 1), 256, SM4>>>(
                ah, al, whl, wll, hf, asrc[L], adst[L], sb, db, smL, N, K, HC, H);

        switch (H) {
            case 4:
                agg_kernel<4, 0><<<aggb, 256>>>(hf, sb, db, smL, bs[L],
                                                nullptr, ah, al, N);
                break;
            case 2:
                agg_kernel<2, 0><<<aggb, 256>>>(hf, sb, db, smL, bs[L],
                                                nullptr, ah, al, N);
                break;
            default:
                agg_kernel<1, 1><<<aggb, 256>>>(hf, sb, db, smL, bs[L],
                                                (float*)d_out, nullptr, nullptr, N);
                break;
        }
    }
}

// round 15
// speedup vs baseline: 1.0565x; 1.0162x over previous
#include <cuda_runtime.h>
#include <cuda_bf16.h>
#include <cuda_fp16.h>
#include <math.h>
#include <stdint.h>

// ---------------------------------------------------------------------------
// GAT, 4 layers. N=50000, E=400000, F=256.
// Layers: 256->8x32, 256->4x32, 128->2x32, 64->1x32 (+ final log_softmax).
// ---------------------------------------------------------------------------
#define MAXN 50000
#define MAXE 400000

__device__ __half g_hf[MAXN * 256];            // h fp16 (agg gathers + self)
__device__ __nv_bfloat16 g_ah[MAXN * 256];     // layer input, bf16 high
__device__ __nv_bfloat16 g_al[MAXN * 256];     // layer input, bf16 low
__device__ __nv_bfloat16 g_wh[108544];         // all 4 W's, bf16 high
__device__ __nv_bfloat16 g_wl[108544];         // all 4 W's, bf16 low
__device__ float g_s[MAXN * 8];
__device__ float g_d[MAXN * 8];
__device__ float g_smax[32];                   // 4 layers x 8 heads
__device__ int   g_deg[MAXN];
__device__ int   g_rowptr[MAXN + 1];
__device__ int   g_cur[MAXN];
__device__ int   g_col[MAXE];
__device__ int   g_bsum[1024];
__device__ int   g_boff[1024];
__device__ int   g_is64;

// ---------------------------------------------------------------------------
// prep: all fp32 -> bf16(h,l) splits in one kernel + smax init
// ---------------------------------------------------------------------------
struct PrepArgs {
    const float* src[5];
    __nv_bfloat16* oh[5];
    __nv_bfloat16* ol[5];
    int start4[5];
    int total4;
};

__global__ void prep_kernel(PrepArgs a) {
    if (blockIdx.x == 0 && threadIdx.x < 32) g_smax[threadIdx.x] = -1e30f;
    int i = blockIdx.x * 256 + threadIdx.x;
    if (i >= a.total4) return;
    int seg = 0;
    #pragma unroll
    for (int k = 1; k < 5; ++k) if (i >= a.start4[k]) seg = k;
    int j = i - a.start4[seg];
    float4 f = reinterpret_cast<const float4*>(a.src[seg])[j];
    __nv_bfloat16 h0 = __float2bfloat16(f.x), h1 = __float2bfloat16(f.y);
    __nv_bfloat16 h2 = __float2bfloat16(f.z), h3 = __float2bfloat16(f.w);
    reinterpret_cast<__nv_bfloat162*>(a.oh[seg])[2 * j]     = __nv_bfloat162(h0, h1);
    reinterpret_cast<__nv_bfloat162*>(a.oh[seg])[2 * j + 1] = __nv_bfloat162(h2, h3);
    reinterpret_cast<__nv_bfloat162*>(a.ol[seg])[2 * j] = __nv_bfloat162(
        __float2bfloat16(f.x - __bfloat162float(h0)),
        __float2bfloat16(f.y - __bfloat162float(h1)));
    reinterpret_cast<__nv_bfloat162*>(a.ol[seg])[2 * j + 1] = __nv_bfloat162(
        __float2bfloat16(f.z - __bfloat162float(h2)),
        __float2bfloat16(f.w - __bfloat162float(h3)));
}

// ---------------------------------------------------------------------------
// CSR build (by dst)
// ---------------------------------------------------------------------------
__global__ void detzero_kernel(const int* __restrict__ ei32, int E, int N) {
    int i = blockIdx.x * blockDim.x + threadIdx.x;
    if (i < N) g_deg[i] = 0;
    if (blockIdx.x == 0 && threadIdx.x == 0) {
        int all_zero = 1;
        for (int k = 1; k < 64 && k < 2 * E; k += 2)
            if (ei32[k] != 0) { all_zero = 0; break; }
        g_is64 = all_zero;
    }
}

__device__ __forceinline__ int edge_val(const void* ei, int E, int which, int e) {
    if (g_is64) {
        const long long* p = (const long long*)ei;
        return (int)p[(size_t)which * E + e];
    } else {
        const int* p = (const int*)ei;
        return p[(size_t)which * E + e];
    }
}

__global__ void hist_kernel(const void* __restrict__ ei, int E) {
    int e = blockIdx.x * blockDim.x + threadIdx.x;
    if (e < E) atomicAdd(&g_deg[edge_val(ei, E, 1, e)], 1);
}

__global__ void scan1_kernel(int N) {
    __shared__ int ws[16];
    int tid = threadIdx.x;                 // 512 threads
    int lane = tid & 31, warp = tid >> 5;
    int i = blockIdx.x * 512 + tid;
    int v = (i < N) ? g_deg[i] : 0;
    int x = v;
    #pragma unroll
    for (int off = 1; off < 32; off <<= 1) {
        int y = __shfl_up_sync(0xFFFFFFFFu, x, off);
        if (lane >= off) x += y;
    }
    if (lane == 31) ws[warp] = x;
    __syncthreads();
    if (tid < 16) {
        int y = ws[tid];
        #pragma unroll
        for (int off = 1; off < 16; off <<= 1) {
            int z = __shfl_up_sync(0x0000FFFFu, y, off);
            if (tid >= off) y += z;
        }
        ws[tid] = y;
    }
    __syncthreads();
    int woff = (warp > 0) ? ws[warp - 1] : 0;
    if (i < N) g_rowptr[i] = x - v + woff;
    if (tid == 0) g_bsum[blockIdx.x] = ws[15];
}

__global__ void scan2_kernel(int nb, int N) {
    __shared__ int ws[4];
    int tid = threadIdx.x;                 // 128 threads, nb <= 128
    int lane = tid & 31, warp = tid >> 5;
    int v = (tid < nb) ? g_bsum[tid] : 0;
    int x = v;
    #pragma unroll
    for (int off = 1; off < 32; off <<= 1) {
        int y = __shfl_up_sync(0xFFFFFFFFu, x, off);
        if (lane >= off) x += y;
    }
    if (lane == 31) ws[warp] = x;
    __syncthreads();
    if (tid < 4) {
        int y = ws[tid];
        #pragma unroll
        for (int off = 1; off < 4; off <<= 1) {
            int z = __shfl_up_sync(0x0000000Fu, y, off);
            if (tid >= off) y += z;
        }
        ws[tid] = y;
    }
    __syncthreads();
    int woff = (warp > 0) ? ws[warp - 1] : 0;
    g_boff[tid] = x - v + woff;
    if (tid == 127) g_rowptr[N] = x + woff;
}

__global__ void scan3_kernel(int N) {
    int i = blockIdx.x * 512 + threadIdx.x;
    if (i < N) {
        int val = g_rowptr[i] + g_boff[blockIdx.x];
        g_rowptr[i] = val;
        g_cur[i] = val;
    }
}

__global__ void scatter_kernel(const void* __restrict__ ei, int E) {
    int e = blockIdx.x * blockDim.x + threadIdx.x;
    if (e < E) {
        int d = edge_val(ei, E, 1, e);
        int s = edge_val(ei, E, 0, e);
        g_col[atomicAdd(&g_cur[d], 1)] = s;
    }
}

__device__ __forceinline__ void atomicMaxFloat(float* addr, float val) {
    if (val >= 0.f) atomicMax((int*)addr, __float_as_int(val));
    else atomicMin((unsigned int*)addr, __float_as_uint(val));
}

// ---------------------------------------------------------------------------
// Tensor-core GEMM: BK=32, 2-stage cp.async, dynamic smem, fused sd/smax
// epilogue, fp16 output. C = Ah*Bh + Al*Bh + Ah*Bl (fp32 accum).
// ---------------------------------------------------------------------------
__device__ __forceinline__ void ldsm_x4(uint32_t& r0, uint32_t& r1, uint32_t& r2,
                                        uint32_t& r3, uint32_t addr) {
    asm volatile("ldmatrix.sync.aligned.m8n8.x4.shared.b16 {%0,%1,%2,%3}, [%4];\n"
                 : "=r"(r0), "=r"(r1), "=r"(r2), "=r"(r3) : "r"(addr));
}
__device__ __forceinline__ void ldsm_x4_t(uint32_t& r0, uint32_t& r1, uint32_t& r2,
                                          uint32_t& r3, uint32_t addr) {
    asm volatile("ldmatrix.sync.aligned.m8n8.x4.trans.shared.b16 {%0,%1,%2,%3}, [%4];\n"
                 : "=r"(r0), "=r"(r1), "=r"(r2), "=r"(r3) : "r"(addr));
}
__device__ __forceinline__ void mma_bf16(float* c, const uint32_t* a,
                                         uint32_t b0, uint32_t b1) {
    asm volatile(
        "mma.sync.aligned.m16n8k16.row.col.f32.bf16.bf16.f32 "
        "{%0,%1,%2,%3}, {%4,%5,%6,%7}, {%8,%9}, {%0,%1,%2,%3};\n"
        : "+f"(c[0]), "+f"(c[1]), "+f"(c[2]), "+f"(c[3])
        : "r"(a[0]), "r"(a[1]), "r"(a[2]), "r"(a[3]), "r"(b0), "r"(b1));
}
__device__ __forceinline__ void cp16(void* dst, const void* src) {
    uint32_t d = (uint32_t)__cvta_generic_to_shared(dst);
    asm volatile("cp.async.cg.shared.global [%0], [%1], 16;\n" :: "r"(d), "l"(src));
}

template <int BM, int BN, int WARPS_M, int WARPS_N, int WM>
__global__ __launch_bounds__(256, 2)
void gemm_mma_kernel(const __nv_bfloat16* __restrict__ Ahg,
                     const __nv_bfloat16* __restrict__ Alg,
                     const __nv_bfloat16* __restrict__ Bhg,
                     const __nv_bfloat16* __restrict__ Blg,
                     __half* __restrict__ Cf,
                     const float* __restrict__ a_src, const float* __restrict__ a_dst,
                     float* __restrict__ s, float* __restrict__ d,
                     float* __restrict__ smax,
                     int M, int K, int N, int H) {
    constexpr int BK = 32;
    constexpr int AP = 40;                 // 80B row stride
    constexpr int BP = BN + 8;
    constexpr int ASZ = BM * AP;
    constexpr int BSZ = BK * BP;
    constexpr int STAGE = 2 * ASZ + 2 * BSZ;
    extern __shared__ __align__(16) __nv_bfloat16 smem[];

    int tid = threadIdx.x, lane = tid & 31, warp = tid >> 5;
    int wm = warp % WARPS_M, wn = warp / WARPS_M;
    int wrow = wm * (WM * 16);
    int wcol = wn * 32;
    int m0 = blockIdx.x * BM, n0 = blockIdx.y * BN;

    float c[WM][4][4] = {};

    auto load = [&](int st, int k0) {
        __nv_bfloat16* sAh = smem + st * STAGE;
        __nv_bfloat16* sAl = sAh + ASZ;
        __nv_bfloat16* sBh = sAl + ASZ;
        __nv_bfloat16* sBl = sBh + BSZ;
        #pragma unroll
        for (int v = tid; v < BM * 4; v += 256) {
            int row = v >> 2, ch = (v & 3) * 8;
            int gm = m0 + row; if (gm >= M) gm = M - 1;  // clamp; stores guarded
            cp16(sAh + row * AP + ch, Ahg + (size_t)gm * K + k0 + ch);
            cp16(sAl + row * AP + ch, Alg + (size_t)gm * K + k0 + ch);
        }
        constexpr int BCH = BN / 8;
        #pragma unroll
        for (int v = tid; v < BK * BCH; v += 256) {
            int row = v / BCH, ch = (v % BCH) * 8;
            cp16(sBh + row * BP + ch, Bhg + (size_t)(k0 + row) * N + n0 + ch);
            cp16(sBl + row * BP + ch, Blg + (size_t)(k0 + row) * N + n0 + ch);
        }
        asm volatile("cp.async.commit_group;\n");
    };

    load(0, 0);
    int nT = K / BK;
    for (int t = 0; t < nT; ++t) {
        int st = t & 1;
        if (t + 1 < nT) {
            load(st ^ 1, (t + 1) * BK);
            asm volatile("cp.async.wait_group 1;\n");
        } else {
            asm volatile("cp.async.wait_group 0;\n");
        }
        __syncthreads();

        const __nv_bfloat16* sAh = smem + st * STAGE;
        const __nv_bfloat16* sAl = sAh + ASZ;
        const __nv_bfloat16* sBh = sAl + ASZ;
        const __nv_bfloat16* sBl = sBh + BSZ;

        #pragma unroll
        for (int kkh = 0; kkh < 2; ++kkh) {
            int kk = kkh * 16;
            uint32_t ah[WM][4], al[WM][4], bh[2][4], bl[2][4];
            #pragma unroll
            for (int im = 0; im < WM; ++im) {
                int r = wrow + im * 16 + (lane & 15);
                ldsm_x4(ah[im][0], ah[im][1], ah[im][2], ah[im][3],
                    (uint32_t)__cvta_generic_to_shared(
                        sAh + r * AP + kk + (lane >> 4) * 8));
                ldsm_x4(al[im][0], al[im][1], al[im][2], al[im][3],
                    (uint32_t)__cvta_generic_to_shared(
                        sAl + r * AP + kk + (lane >> 4) * 8));
            }
            #pragma unroll
            for (int jn = 0; jn < 2; ++jn) {
                int r = kk + (lane & 15);
                int cc = wcol + jn * 16 + (lane >> 4) * 8;
                ldsm_x4_t(bh[jn][0], bh[jn][1], bh[jn][2], bh[jn][3],
                    (uint32_t)__cvta_generic_to_shared(sBh + r * BP + cc));
                ldsm_x4_t(bl[jn][0], bl[jn][1], bl[jn][2], bl[jn][3],
                    (uint32_t)__cvta_generic_to_shared(sBl + r * BP + cc));
            }
            #pragma unroll
            for (int im = 0; im < WM; ++im) {
                #pragma unroll
                for (int j = 0; j < 4; ++j) {
                    uint32_t b0h = bh[j >> 1][(j & 1) * 2];
                    uint32_t b1h = bh[j >> 1][(j & 1) * 2 + 1];
                    uint32_t b0l = bl[j >> 1][(j & 1) * 2];
                    uint32_t b1l = bl[j >> 1][(j & 1) * 2 + 1];
                    mma_bf16(c[im][j], ah[im], b0h, b1h);
                    mma_bf16(c[im][j], al[im], b0h, b1h);
                    mma_bf16(c[im][j], ah[im], b0l, b1l);
                }
            }
        }
        __syncthreads();
    }

    // --- epilogue: fp16 store ---
    #pragma unroll
    for (int im = 0; im < WM; ++im) {
        #pragma unroll
        for (int j = 0; j < 4; ++j) {
            int r = wrow + im * 16 + (lane >> 2);
            int col = n0 + wcol + j * 8 + (lane & 3) * 2;
            int gr = m0 + r;
            if (gr < M)
                *reinterpret_cast<__half2*>(&Cf[(size_t)gr * N + col]) =
                    __floats2half2_rn(c[im][j][0], c[im][j][1]);
            if (gr + 8 < M)
                *reinterpret_cast<__half2*>(&Cf[(size_t)(gr + 8) * N + col]) =
                    __floats2half2_rn(c[im][j][2], c[im][j][3]);
        }
    }

    // --- fused s/d dots + smax (warp tile == one head's 32 columns) ---
    int head = (n0 + wcol) >> 5;
    float asv[8], adv[8];
    #pragma unroll
    for (int j = 0; j < 4; ++j)
        #pragma unroll
        for (int q = 0; q < 2; ++q) {
            int cc = j * 8 + (lane & 3) * 2 + q;
            asv[j * 2 + q] = a_src[head * 32 + cc];
            adv[j * 2 + q] = a_dst[head * 32 + cc];
        }
    float wmax = -1e30f;
    #pragma unroll
    for (int im = 0; im < WM; ++im) {
        float s1 = 0.f, d1 = 0.f, s2 = 0.f, d2 = 0.f;
        #pragma unroll
        for (int j = 0; j < 4; ++j)
            #pragma unroll
            for (int q = 0; q < 2; ++q) {
                float av = asv[j * 2 + q], dv = adv[j * 2 + q];
                s1 = fmaf(c[im][j][q],     av, s1);
                d1 = fmaf(c[im][j][q],     dv, d1);
                s2 = fmaf(c[im][j][2 + q], av, s2);
                d2 = fmaf(c[im][j][2 + q], dv, d2);
            }
        #pragma unroll
        for (int off = 1; off <= 2; off <<= 1) {
            s1 += __shfl_xor_sync(0xFFFFFFFFu, s1, off);
            d1 += __shfl_xor_sync(0xFFFFFFFFu, d1, off);
            s2 += __shfl_xor_sync(0xFFFFFFFFu, s2, off);
            d2 += __shfl_xor_sync(0xFFFFFFFFu, d2, off);
        }
        int r1 = m0 + wrow + im * 16 + (lane >> 2);
        if ((lane & 3) == 0) {
            if (r1 < M) {
                s[(size_t)r1 * H + head] = s1;
                d[(size_t)r1 * H + head] = d1;
                wmax = fmaxf(wmax, s1);
            }
            if (r1 + 8 < M) {
                s[(size_t)(r1 + 8) * H + head] = s2;
                d[(size_t)(r1 + 8) * H + head] = d2;
                wmax = fmaxf(wmax, s2);
            }
        }
    }
    #pragma unroll
    for (int off = 16; off > 0; off >>= 1)
        wmax = fmaxf(wmax, __shfl_xor_sync(0xFFFFFFFFu, wmax, off));
    if (lane == 0) atomicMaxFloat(&smax[head], wmax);
}

// ---------------------------------------------------------------------------
// Aggregation: one warp per NODE (scalar R10 layout). Fixed softmax shift
// m_h = leaky(smax_h + d_n,h) >= every edge score.
// Two-phase super-chunks: phase A computes edge weights for up to NCH chunks
// with independent (clamped, branch-free) col/s loads so ptxas batches them
// (MLP = NCH); phase B then issues all h-row gathers (fully independent).
// This breaks the per-chunk serial col->s->exp->gather dependency chain.
// ---------------------------------------------------------------------------
template <int H, int NCH, int ACT>
__global__ void agg_kernel(const __half* __restrict__ hf,
                           const float* __restrict__ s,
                           const float* __restrict__ d, const float* __restrict__ smax,
                           const float* __restrict__ bias,
                           float* __restrict__ outf, __nv_bfloat16* __restrict__ outh,
                           __nv_bfloat16* __restrict__ outl, int N) {
    constexpr int HC = H * 32;
    constexpr int EC = 32 / H;              // edges per chunk
    int n = blockIdx.x * 8 + (threadIdx.x >> 5);
    int lane = threadIdx.x & 31;
    if (n >= N) return;
    int eidx = lane / H;
    int hidx = lane % H;

    float dnh = d[(size_t)n * H + hidx];
    float mh = smax[hidx] + dnh;
    mh = (mh > 0.f) ? mh : 0.2f * mh;

    float den[H], acc[H];
    #pragma unroll
    for (int k = 0; k < H; ++k) {
        float mk = __shfl_sync(0xFFFFFFFFu, mh, k);    // lane k holds head k
        float e0 = s[(size_t)n * H + k] + d[(size_t)n * H + k];
        e0 = (e0 > 0.f) ? e0 : 0.2f * e0;
        float w0 = __expf(e0 - mk);
        den[k] = w0;
        acc[k] = w0 * __half2float(hf[(size_t)n * HC + hidx * 32 + lane]);
    }
    // NOTE: self contribution must use head k's row; redo correctly below.
    // (overwrite: acc[k] computed with hidx row is wrong for k != hidx)
    #pragma unroll
    for (int k = 0; k < H; ++k)
        acc[k] = den[k] * __half2float(hf[(size_t)n * HC + k * 32 + lane]);

    float edgeden = 0.f;
    int r0 = g_rowptr[n], r1 = g_rowptr[n + 1];
    for (int base = r0; base < r1; base += EC * NCH) {
        int total = r1 - base; if (total > EC * NCH) total = EC * NCH;
        int nch = (total + EC - 1) / EC;

        // --- phase A: edge weights for up to NCH chunks (branch-free) ---
        int srcr[NCH]; float wr[NCH];
        #pragma unroll
        for (int c = 0; c < NCH; ++c) {
            int off = c * EC + eidx;
            int offc = (off < total) ? off : (total - 1);   // clamp: safe load
            srcr[c] = g_col[base + offc];
        }
        #pragma unroll
        for (int c = 0; c < NCH; ++c) {
            float e = s[(size_t)srcr[c] * H + hidx] + dnh;
            e = (e > 0.f) ? e : 0.2f * e;
            float w = __expf(e - mh);
            if (c * EC + eidx >= total) w = 0.f;
            wr[c] = w;
            edgeden += w;
        }

        // --- phase B: h-row gathers (all independent) ---
        #pragma unroll
        for (int c = 0; c < NCH; ++c) {
            if (c >= nch) break;
            int cb = c * EC;
            #pragma unroll
            for (int j = 0; j < EC; ++j) {
                if (cb + j >= total) break;
                int sj = __shfl_sync(0xFFFFFFFFu, srcr[c], j * H);
                const __half* hp = hf + (size_t)sj * HC + lane;
                #pragma unroll
                for (int k = 0; k < H; ++k) {
                    float wk = __shfl_sync(0xFFFFFFFFu, wr[c], j * H + k);
                    acc[k] = fmaf(wk, __half2float(hp[k * 32]), acc[k]);
                }
            }
        }
    }
    // reduce per-lane edge denominators across edge slots (same head)
    #pragma unroll
    for (int off = H; off < 32; off <<= 1)
        edgeden += __shfl_xor_sync(0xFFFFFFFFu, edgeden, off);
    #pragma unroll
    for (int k = 0; k < H; ++k)
        den[k] += __shfl_sync(0xFFFFFFFFu, edgeden, k);

    if (ACT == 0) {
        #pragma unroll
        for (int k = 0; k < H; ++k) {
            float o = acc[k] / den[k] + bias[k * 32 + lane];
            o = (o > 0.f) ? o : expm1f(o);                  // ELU
            size_t idx = (size_t)n * HC + k * 32 + lane;
            __nv_bfloat16 oh = __float2bfloat16(o);
            outh[idx] = oh;
            outl[idx] = __float2bfloat16(o - __bfloat162float(oh));
        }
    } else {
        float o = acc[0] / den[0] + bias[lane];
        float mx = o;
        #pragma unroll
        for (int off = 16; off > 0; off >>= 1)
            mx = fmaxf(mx, __shfl_xor_sync(0xFFFFFFFFu, mx, off));
        float ex = __expf(o - mx);
        float sum = ex;
        #pragma unroll
        for (int off = 16; off > 0; off >>= 1)
            sum += __shfl_xor_sync(0xFFFFFFFFu, sum, off);
        outf[(size_t)n * 32 + lane] = o - mx - logf(sum);
    }
}

// ---------------------------------------------------------------------------
// Launch (single stream; R10 structure).
// ---------------------------------------------------------------------------
extern "C" void kernel_launch(void* const* d_in, const int* in_sizes, int n_in,
                              void* d_out, int out_size) {
    const float* x  = (const float*)d_in[0];
    const void*  ei = d_in[1];
    const float* W[4]    = {(const float*)d_in[2],  (const float*)d_in[6],
                            (const float*)d_in[10], (const float*)d_in[14]};
    const float* asrc[4] = {(const float*)d_in[3],  (const float*)d_in[7],
                            (const float*)d_in[11], (const float*)d_in[15]};
    const float* adst[4] = {(const float*)d_in[4],  (const float*)d_in[8],
                            (const float*)d_in[12], (const float*)d_in[16]};
    const float* bs[4]   = {(const float*)d_in[5],  (const float*)d_in[9],
                            (const float*)d_in[13], (const float*)d_in[17]};

    int N = in_sizes[0] / 256;
    int E = in_sizes[1] / 2;

    float *sb, *db, *smaxb;
    __half *hf;
    __nv_bfloat16 *ah, *al, *wh, *wl;
    cudaGetSymbolAddress((void**)&hf,    g_hf);
    cudaGetSymbolAddress((void**)&sb,    g_s);
    cudaGetSymbolAddress((void**)&db,    g_d);
    cudaGetSymbolAddress((void**)&smaxb, g_smax);
    cudaGetSymbolAddress((void**)&ah,    g_ah);
    cudaGetSymbolAddress((void**)&al,    g_al);
    cudaGetSymbolAddress((void**)&wh,    g_wh);
    cudaGetSymbolAddress((void**)&wl,    g_wl);

    const int Hs[4]   = {8, 4, 2, 1};
    const int Ks[4]   = {256, 256, 128, 64};
    const int HCs[4]  = {256, 128, 64, 32};
    const int woff[4] = {0, 65536, 98304, 106496};

    const int SM1 = (2 * 96 * 40 + 2 * 32 * 136) * 2 * 2;    // 65536
    const int SM3 = (2 * 128 * 40 + 2 * 32 * 72) * 2 * 2;    // 59392
    const int SM4 = (2 * 128 * 40 + 2 * 32 * 40) * 2 * 2;    // 51200
    cudaFuncSetAttribute(gemm_mma_kernel<96, 128, 2, 4, 3>,
                         cudaFuncAttributeMaxDynamicSharedMemorySize, SM1);
    cudaFuncSetAttribute(gemm_mma_kernel<128, 64, 4, 2, 2>,
                         cudaFuncAttributeMaxDynamicSharedMemorySize, SM3);
    cudaFuncSetAttribute(gemm_mma_kernel<128, 32, 8, 1, 1>,
                         cudaFuncAttributeMaxDynamicSharedMemorySize, SM4);

    int gx96 = (N + 95) / 96;
    int gx128 = (N + 127) / 128;
    int aggb = (N + 7) / 8;
    int nb = (N + 511) / 512;

    PrepArgs pa;
    pa.src[0] = x;    pa.oh[0] = ah; pa.ol[0] = al;
    int acc4 = N * 256 / 4;
    pa.start4[0] = 0;
    for (int L = 0; L < 4; ++L) {
        pa.src[L + 1] = W[L];
        pa.oh[L + 1] = wh + woff[L];
        pa.ol[L + 1] = wl + woff[L];
        pa.start4[L + 1] = acc4;
        acc4 += Ks[L] * HCs[L] / 4;
    }
    pa.total4 = acc4;

    prep_kernel<<<(pa.total4 + 255) / 256, 256>>>(pa);                    // 0
    detzero_kernel<<<(N + 255) / 256, 256>>>((const int*)ei, E, N);       // 1
    hist_kernel<<<(E + 255) / 256, 256>>>(ei, E);                         // 2
    gemm_mma_kernel<96, 128, 2, 4, 3><<<dim3(gx96, 2), 256, SM1>>>(       // 3
        ah, al, wh, wl, hf, asrc[0], adst[0], sb, db, smaxb, N, 256, 256, 8);
    scan1_kernel<<<nb, 512>>>(N);
    scan2_kernel<<<1, 128>>>(nb, N);
    scan3_kernel<<<nb, 512>>>(N);
    scatter_kernel<<<(E + 255) / 256, 256>>>(ei, E);

    // --- layer 1 aggregation ---
    agg_kernel<8, 4, 0><<<aggb, 256>>>(hf, sb, db, smaxb, bs[0], nullptr, ah, al, N);

    // --- layers 2-4 ---
    for (int L = 1; L < 4; ++L) {
        int K = Ks[L], HC = HCs[L], H = Hs[L];
        const __nv_bfloat16* whl = wh + woff[L];
        const __nv_bfloat16* wll = wl + woff[L];
        float* smL = smaxb + L * 8;
        if (L == 1)
            gemm_mma_kernel<96, 128, 2, 4, 3><<<dim3(gx96, 1), 256, SM1>>>(
                ah, al, whl, wll, hf, asrc[L], adst[L], sb, db, smL, N, K, HC, H);
        else if (L == 2)
            gemm_mma_kernel<128, 64, 4, 2, 2><<<dim3(gx128, 1), 256, SM3>>>(
                ah, al, whl, wll, hf, asrc[L], adst[L], sb, db, smL, N, K, HC, H);
        else
            gemm_mma_kernel<128, 32, 8, 1, 1><<<dim3(gx128, 1), 256, SM4>>>(
                ah, al, whl, wll, hf, asrc[L], adst[L], sb, db, smL, N, K, HC, H);

        switch (H) {
            case 4:
                agg_kernel<4, 2, 0><<<aggb, 256>>>(hf, sb, db, smL, bs[L],
                                                   nullptr, ah, al, N);
                break;
            case 2:
                agg_kernel<2, 1, 0><<<aggb, 256>>>(hf, sb, db, smL, bs[L],
                                                   nullptr, ah, al, N);
                break;
            default:
                agg_kernel<1, 1, 1><<<aggb, 256>>>(hf, sb, db, smL, bs[L],
                                                   (float*)d_out, nullptr, nullptr, N);
                break;
        }
    }
}

// round 16
// speedup vs baseline: 1.1742x; 1.1113x over previous
#include <cuda_runtime.h>
#include <cuda_bf16.h>
#include <cuda_fp16.h>
#include <math.h>
#include <stdint.h>

// ---------------------------------------------------------------------------
// GAT, 4 layers. N=50000, E=400000, F=256.
// Layers: 256->8x32, 256->4x32, 128->2x32, 64->1x32 (+ final log_softmax).
// GEMM: C = Ah*Bh + Ah*Bl  (B split exact to bf16 pair; A rounded to bf16).
// ---------------------------------------------------------------------------
#define MAXN 50000
#define MAXE 400000

__device__ __half g_hf[MAXN * 256];            // h fp16 (agg gathers + self)
__device__ __nv_bfloat16 g_ah[MAXN * 256];     // layer input, bf16 (A high only)
__device__ __nv_bfloat16 g_wh[108544];         // all 4 W's, bf16 high
__device__ __nv_bfloat16 g_wl[108544];         // all 4 W's, bf16 low
__device__ float g_s[MAXN * 8];
__device__ float g_d[MAXN * 8];
__device__ float g_smax[32];                   // 4 layers x 8 heads
__device__ int   g_deg[MAXN];
__device__ int   g_rowptr[MAXN + 1];
__device__ int   g_cur[MAXN];
__device__ int   g_col[MAXE];
__device__ int   g_bsum[1024];
__device__ int   g_boff[1024];
__device__ int   g_is64;

// ---------------------------------------------------------------------------
// prep: fp32 -> bf16 splits (x: high only; W: high+low) + smax init
// ---------------------------------------------------------------------------
struct PrepArgs {
    const float* src[5];
    __nv_bfloat16* oh[5];
    __nv_bfloat16* ol[5];      // nullptr -> skip low part
    int start4[5];
    int total4;
};

__global__ void prep_kernel(PrepArgs a) {
    if (blockIdx.x == 0 && threadIdx.x < 32) g_smax[threadIdx.x] = -1e30f;
    int i = blockIdx.x * 256 + threadIdx.x;
    if (i >= a.total4) return;
    int seg = 0;
    #pragma unroll
    for (int k = 1; k < 5; ++k) if (i >= a.start4[k]) seg = k;
    int j = i - a.start4[seg];
    float4 f = reinterpret_cast<const float4*>(a.src[seg])[j];
    __nv_bfloat16 h0 = __float2bfloat16(f.x), h1 = __float2bfloat16(f.y);
    __nv_bfloat16 h2 = __float2bfloat16(f.z), h3 = __float2bfloat16(f.w);
    reinterpret_cast<__nv_bfloat162*>(a.oh[seg])[2 * j]     = __nv_bfloat162(h0, h1);
    reinterpret_cast<__nv_bfloat162*>(a.oh[seg])[2 * j + 1] = __nv_bfloat162(h2, h3);
    if (a.ol[seg]) {
        reinterpret_cast<__nv_bfloat162*>(a.ol[seg])[2 * j] = __nv_bfloat162(
            __float2bfloat16(f.x - __bfloat162float(h0)),
            __float2bfloat16(f.y - __bfloat162float(h1)));
        reinterpret_cast<__nv_bfloat162*>(a.ol[seg])[2 * j + 1] = __nv_bfloat162(
            __float2bfloat16(f.z - __bfloat162float(h2)),
            __float2bfloat16(f.w - __bfloat162float(h3)));
    }
}

// ---------------------------------------------------------------------------
// CSR build (by dst)
// ---------------------------------------------------------------------------
__global__ void detzero_kernel(const int* __restrict__ ei32, int E, int N) {
    int i = blockIdx.x * blockDim.x + threadIdx.x;
    if (i < N) g_deg[i] = 0;
    if (blockIdx.x == 0 && threadIdx.x == 0) {
        int all_zero = 1;
        for (int k = 1; k < 64 && k < 2 * E; k += 2)
            if (ei32[k] != 0) { all_zero = 0; break; }
        g_is64 = all_zero;
    }
}

__device__ __forceinline__ int edge_val(const void* ei, int E, int which, int e) {
    if (g_is64) {
        const long long* p = (const long long*)ei;
        return (int)p[(size_t)which * E + e];
    } else {
        const int* p = (const int*)ei;
        return p[(size_t)which * E + e];
    }
}

__global__ void hist_kernel(const void* __restrict__ ei, int E) {
    int e = blockIdx.x * blockDim.x + threadIdx.x;
    if (e < E) atomicAdd(&g_deg[edge_val(ei, E, 1, e)], 1);
}

__global__ void scan1_kernel(int N) {
    __shared__ int ws[16];
    int tid = threadIdx.x;                 // 512 threads
    int lane = tid & 31, warp = tid >> 5;
    int i = blockIdx.x * 512 + tid;
    int v = (i < N) ? g_deg[i] : 0;
    int x = v;
    #pragma unroll
    for (int off = 1; off < 32; off <<= 1) {
        int y = __shfl_up_sync(0xFFFFFFFFu, x, off);
        if (lane >= off) x += y;
    }
    if (lane == 31) ws[warp] = x;
    __syncthreads();
    if (tid < 16) {
        int y = ws[tid];
        #pragma unroll
        for (int off = 1; off < 16; off <<= 1) {
            int z = __shfl_up_sync(0x0000FFFFu, y, off);
            if (tid >= off) y += z;
        }
        ws[tid] = y;
    }
    __syncthreads();
    int woff = (warp > 0) ? ws[warp - 1] : 0;
    if (i < N) g_rowptr[i] = x - v + woff;
    if (tid == 0) g_bsum[blockIdx.x] = ws[15];
}

__global__ void scan2_kernel(int nb, int N) {
    __shared__ int ws[4];
    int tid = threadIdx.x;                 // 128 threads, nb <= 128
    int lane = tid & 31, warp = tid >> 5;
    int v = (tid < nb) ? g_bsum[tid] : 0;
    int x = v;
    #pragma unroll
    for (int off = 1; off < 32; off <<= 1) {
        int y = __shfl_up_sync(0xFFFFFFFFu, x, off);
        if (lane >= off) x += y;
    }
    if (lane == 31) ws[warp] = x;
    __syncthreads();
    if (tid < 4) {
        int y = ws[tid];
        #pragma unroll
        for (int off = 1; off < 4; off <<= 1) {
            int z = __shfl_up_sync(0x0000000Fu, y, off);
            if (tid >= off) y += z;
        }
        ws[tid] = y;
    }
    __syncthreads();
    int woff = (warp > 0) ? ws[warp - 1] : 0;
    g_boff[tid] = x - v + woff;
    if (tid == 127) g_rowptr[N] = x + woff;
}

__global__ void scan3_kernel(int N) {
    int i = blockIdx.x * 512 + threadIdx.x;
    if (i < N) {
        int val = g_rowptr[i] + g_boff[blockIdx.x];
        g_rowptr[i] = val;
        g_cur[i] = val;
    }
}

__global__ void scatter_kernel(const void* __restrict__ ei, int E) {
    int e = blockIdx.x * blockDim.x + threadIdx.x;
    if (e < E) {
        int d = edge_val(ei, E, 1, e);
        int s = edge_val(ei, E, 0, e);
        g_col[atomicAdd(&g_cur[d], 1)] = s;
    }
}

__device__ __forceinline__ void atomicMaxFloat(float* addr, float val) {
    if (val >= 0.f) atomicMax((int*)addr, __float_as_int(val));
    else atomicMin((unsigned int*)addr, __float_as_uint(val));
}

// ---------------------------------------------------------------------------
// Tensor-core GEMM: BK=32, 2-stage cp.async, dynamic smem, fused sd/smax
// epilogue, fp16 output. C = Ah*Bh + Ah*Bl (A bf16-high only; fp32 accum).
// ---------------------------------------------------------------------------
__device__ __forceinline__ void ldsm_x4(uint32_t& r0, uint32_t& r1, uint32_t& r2,
                                        uint32_t& r3, uint32_t addr) {
    asm volatile("ldmatrix.sync.aligned.m8n8.x4.shared.b16 {%0,%1,%2,%3}, [%4];\n"
                 : "=r"(r0), "=r"(r1), "=r"(r2), "=r"(r3) : "r"(addr));
}
__device__ __forceinline__ void ldsm_x4_t(uint32_t& r0, uint32_t& r1, uint32_t& r2,
                                          uint32_t& r3, uint32_t addr) {
    asm volatile("ldmatrix.sync.aligned.m8n8.x4.trans.shared.b16 {%0,%1,%2,%3}, [%4];\n"
                 : "=r"(r0), "=r"(r1), "=r"(r2), "=r"(r3) : "r"(addr));
}
__device__ __forceinline__ void mma_bf16(float* c, const uint32_t* a,
                                         uint32_t b0, uint32_t b1) {
    asm volatile(
        "mma.sync.aligned.m16n8k16.row.col.f32.bf16.bf16.f32 "
        "{%0,%1,%2,%3}, {%4,%5,%6,%7}, {%8,%9}, {%0,%1,%2,%3};\n"
        : "+f"(c[0]), "+f"(c[1]), "+f"(c[2]), "+f"(c[3])
        : "r"(a[0]), "r"(a[1]), "r"(a[2]), "r"(a[3]), "r"(b0), "r"(b1));
}
__device__ __forceinline__ void cp16(void* dst, const void* src) {
    uint32_t d = (uint32_t)__cvta_generic_to_shared(dst);
    asm volatile("cp.async.cg.shared.global [%0], [%1], 16;\n" :: "r"(d), "l"(src));
}

template <int BM, int BN, int WARPS_M, int WARPS_N, int WM>
__global__ __launch_bounds__(256, 2)
void gemm_mma_kernel(const __nv_bfloat16* __restrict__ Ahg,
                     const __nv_bfloat16* __restrict__ Bhg,
                     const __nv_bfloat16* __restrict__ Blg,
                     __half* __restrict__ Cf,
                     const float* __restrict__ a_src, const float* __restrict__ a_dst,
                     float* __restrict__ s, float* __restrict__ d,
                     float* __restrict__ smax,
                     int M, int K, int N, int H) {
    constexpr int BK = 32;
    constexpr int AP = 40;                 // 80B row stride
    constexpr int BP = BN + 8;
    constexpr int ASZ = BM * AP;
    constexpr int BSZ = BK * BP;
    constexpr int STAGE = ASZ + 2 * BSZ;
    extern __shared__ __align__(16) __nv_bfloat16 smem[];

    int tid = threadIdx.x, lane = tid & 31, warp = tid >> 5;
    int wm = warp % WARPS_M, wn = warp / WARPS_M;
    int wrow = wm * (WM * 16);
    int wcol = wn * 32;
    int m0 = blockIdx.x * BM, n0 = blockIdx.y * BN;

    float c[WM][4][4] = {};

    auto load = [&](int st, int k0) {
        __nv_bfloat16* sAh = smem + st * STAGE;
        __nv_bfloat16* sBh = sAh + ASZ;
        __nv_bfloat16* sBl = sBh + BSZ;
        #pragma unroll
        for (int v = tid; v < BM * 4; v += 256) {
            int row = v >> 2, ch = (v & 3) * 8;
            int gm = m0 + row; if (gm >= M) gm = M - 1;  // clamp; stores guarded
            cp16(sAh + row * AP + ch, Ahg + (size_t)gm * K + k0 + ch);
        }
        constexpr int BCH = BN / 8;
        #pragma unroll
        for (int v = tid; v < BK * BCH; v += 256) {
            int row = v / BCH, ch = (v % BCH) * 8;
            cp16(sBh + row * BP + ch, Bhg + (size_t)(k0 + row) * N + n0 + ch);
            cp16(sBl + row * BP + ch, Blg + (size_t)(k0 + row) * N + n0 + ch);
        }
        asm volatile("cp.async.commit_group;\n");
    };

    load(0, 0);
    int nT = K / BK;
    for (int t = 0; t < nT; ++t) {
        int st = t & 1;
        if (t + 1 < nT) {
            load(st ^ 1, (t + 1) * BK);
            asm volatile("cp.async.wait_group 1;\n");
        } else {
            asm volatile("cp.async.wait_group 0;\n");
        }
        __syncthreads();

        const __nv_bfloat16* sAh = smem + st * STAGE;
        const __nv_bfloat16* sBh = sAh + ASZ;
        const __nv_bfloat16* sBl = sBh + BSZ;

        #pragma unroll
        for (int kkh = 0; kkh < 2; ++kkh) {
            int kk = kkh * 16;
            uint32_t ah[WM][4], bh[2][4], bl[2][4];
            #pragma unroll
            for (int im = 0; im < WM; ++im) {
                int r = wrow + im * 16 + (lane & 15);
                ldsm_x4(ah[im][0], ah[im][1], ah[im][2], ah[im][3],
                    (uint32_t)__cvta_generic_to_shared(
                        sAh + r * AP + kk + (lane >> 4) * 8));
            }
            #pragma unroll
            for (int jn = 0; jn < 2; ++jn) {
                int r = kk + (lane & 15);
                int cc = wcol + jn * 16 + (lane >> 4) * 8;
                ldsm_x4_t(bh[jn][0], bh[jn][1], bh[jn][2], bh[jn][3],
                    (uint32_t)__cvta_generic_to_shared(sBh + r * BP + cc));
                ldsm_x4_t(bl[jn][0], bl[jn][1], bl[jn][2], bl[jn][3],
                    (uint32_t)__cvta_generic_to_shared(sBl + r * BP + cc));
            }
            #pragma unroll
            for (int im = 0; im < WM; ++im) {
                #pragma unroll
                for (int j = 0; j < 4; ++j) {
                    uint32_t b0h = bh[j >> 1][(j & 1) * 2];
                    uint32_t b1h = bh[j >> 1][(j & 1) * 2 + 1];
                    uint32_t b0l = bl[j >> 1][(j & 1) * 2];
                    uint32_t b1l = bl[j >> 1][(j & 1) * 2 + 1];
                    mma_bf16(c[im][j], ah[im], b0h, b1h);
                    mma_bf16(c[im][j], ah[im], b0l, b1l);
                }
            }
        }
        __syncthreads();
    }

    // --- epilogue: fp16 store ---
    #pragma unroll
    for (int im = 0; im < WM; ++im) {
        #pragma unroll
        for (int j = 0; j < 4; ++j) {
            int r = wrow + im * 16 + (lane >> 2);
            int col = n0 + wcol + j * 8 + (lane & 3) * 2;
            int gr = m0 + r;
            if (gr < M)
                *reinterpret_cast<__half2*>(&Cf[(size_t)gr * N + col]) =
                    __floats2half2_rn(c[im][j][0], c[im][j][1]);
            if (gr + 8 < M)
                *reinterpret_cast<__half2*>(&Cf[(size_t)(gr + 8) * N + col]) =
                    __floats2half2_rn(c[im][j][2], c[im][j][3]);
        }
    }

    // --- fused s/d dots + smax (warp tile == one head's 32 columns) ---
    int head = (n0 + wcol) >> 5;
    float asv[8], adv[8];
    #pragma unroll
    for (int j = 0; j < 4; ++j)
        #pragma unroll
        for (int q = 0; q < 2; ++q) {
            int cc = j * 8 + (lane & 3) * 2 + q;
            asv[j * 2 + q] = a_src[head * 32 + cc];
            adv[j * 2 + q] = a_dst[head * 32 + cc];
        }
    float wmax = -1e30f;
    #pragma unroll
    for (int im = 0; im < WM; ++im) {
        float s1 = 0.f, d1 = 0.f, s2 = 0.f, d2 = 0.f;
        #pragma unroll
        for (int j = 0; j < 4; ++j)
            #pragma unroll
            for (int q = 0; q < 2; ++q) {
                float av = asv[j * 2 + q], dv = adv[j * 2 + q];
                s1 = fmaf(c[im][j][q],     av, s1);
                d1 = fmaf(c[im][j][q],     dv, d1);
                s2 = fmaf(c[im][j][2 + q], av, s2);
                d2 = fmaf(c[im][j][2 + q], dv, d2);
            }
        #pragma unroll
        for (int off = 1; off <= 2; off <<= 1) {
            s1 += __shfl_xor_sync(0xFFFFFFFFu, s1, off);
            d1 += __shfl_xor_sync(0xFFFFFFFFu, d1, off);
            s2 += __shfl_xor_sync(0xFFFFFFFFu, s2, off);
            d2 += __shfl_xor_sync(0xFFFFFFFFu, d2, off);
        }
        int r1 = m0 + wrow + im * 16 + (lane >> 2);
        if ((lane & 3) == 0) {
            if (r1 < M) {
                s[(size_t)r1 * H + head] = s1;
                d[(size_t)r1 * H + head] = d1;
                wmax = fmaxf(wmax, s1);
            }
            if (r1 + 8 < M) {
                s[(size_t)(r1 + 8) * H + head] = s2;
                d[(size_t)(r1 + 8) * H + head] = d2;
                wmax = fmaxf(wmax, s2);
            }
        }
    }
    #pragma unroll
    for (int off = 16; off > 0; off >>= 1)
        wmax = fmaxf(wmax, __shfl_xor_sync(0xFFFFFFFFu, wmax, off));
    if (lane == 0) atomicMaxFloat(&smax[head], wmax);
}

// ---------------------------------------------------------------------------
// Aggregation: one warp per NODE (R10 scalar layout — best measured).
// Fixed softmax shift m_h = leaky(smax_h + d_n,h). All h reads fp16.
// ACT 0: bias+ELU, write bf16 high only (next GEMM's A side).
// ACT 1: bias+log_softmax (H==1), write fp32.
// ---------------------------------------------------------------------------
template <int H, int ACT>
__global__ void agg_kernel(const __half* __restrict__ hf,
                           const float* __restrict__ s,
                           const float* __restrict__ d, const float* __restrict__ smax,
                           const float* __restrict__ bias,
                           float* __restrict__ outf, __nv_bfloat16* __restrict__ outh,
                           int N) {
    constexpr int HC = H * 32;
    constexpr int EC = 32 / H;              // edges per chunk
    int n = blockIdx.x * 8 + (threadIdx.x >> 5);
    int lane = threadIdx.x & 31;
    if (n >= N) return;
    int eidx = lane / H;
    int hidx = lane % H;

    float dnh = d[(size_t)n * H + hidx];
    float mh = smax[hidx] + dnh;
    mh = (mh > 0.f) ? mh : 0.2f * mh;

    float den[H], acc[H];
    #pragma unroll
    for (int k = 0; k < H; ++k) {
        float mk = __shfl_sync(0xFFFFFFFFu, mh, k);    // lane k holds head k
        float e0 = s[(size_t)n * H + k] + d[(size_t)n * H + k];
        e0 = (e0 > 0.f) ? e0 : 0.2f * e0;
        float w0 = __expf(e0 - mk);
        den[k] = w0;
        acc[k] = w0 * __half2float(hf[(size_t)n * HC + k * 32 + lane]);
    }

    float edgeden = 0.f;
    int r0 = g_rowptr[n], r1 = g_rowptr[n + 1];
    for (int base = r0; base < r1; base += EC) {
        int cnt = r1 - base; if (cnt > EC) cnt = EC;
        int src = 0; float w = 0.f;
        if (eidx < cnt) {
            src = g_col[base + eidx];
            float e = s[(size_t)src * H + hidx] + dnh;
            e = (e > 0.f) ? e : 0.2f * e;
            w = __expf(e - mh);
            edgeden += w;
        }
        #pragma unroll
        for (int j = 0; j < EC; ++j) {
            if (j >= cnt) break;
            int sj = __shfl_sync(0xFFFFFFFFu, src, j * H);
            const __half* hp = hf + (size_t)sj * HC + lane;
            #pragma unroll
            for (int k = 0; k < H; ++k) {
                float wk = __shfl_sync(0xFFFFFFFFu, w, j * H + k);
                acc[k] = fmaf(wk, __half2float(hp[k * 32]), acc[k]);
            }
        }
    }
    #pragma unroll
    for (int off = H; off < 32; off <<= 1)
        edgeden += __shfl_xor_sync(0xFFFFFFFFu, edgeden, off);
    #pragma unroll
    for (int k = 0; k < H; ++k)
        den[k] += __shfl_sync(0xFFFFFFFFu, edgeden, k);

    if (ACT == 0) {
        #pragma unroll
        for (int k = 0; k < H; ++k) {
            float o = acc[k] / den[k] + bias[k * 32 + lane];
            o = (o > 0.f) ? o : expm1f(o);                  // ELU
            outh[(size_t)n * HC + k * 32 + lane] = __float2bfloat16(o);
        }
    } else {
        float o = acc[0] / den[0] + bias[lane];
        float mx = o;
        #pragma unroll
        for (int off = 16; off > 0; off >>= 1)
            mx = fmaxf(mx, __shfl_xor_sync(0xFFFFFFFFu, mx, off));
        float ex = __expf(o - mx);
        float sum = ex;
        #pragma unroll
        for (int off = 16; off > 0; off >>= 1)
            sum += __shfl_xor_sync(0xFFFFFFFFu, sum, off);
        outf[(size_t)n * 32 + lane] = o - mx - logf(sum);
    }
}

// ---------------------------------------------------------------------------
// Launch (single stream; R10 structure, gemm1 at ncu idx 3).
// ---------------------------------------------------------------------------
extern "C" void kernel_launch(void* const* d_in, const int* in_sizes, int n_in,
                              void* d_out, int out_size) {
    const float* x  = (const float*)d_in[0];
    const void*  ei = d_in[1];
    const float* W[4]    = {(const float*)d_in[2],  (const float*)d_in[6],
                            (const float*)d_in[10], (const float*)d_in[14]};
    const float* asrc[4] = {(const float*)d_in[3],  (const float*)d_in[7],
                            (const float*)d_in[11], (const float*)d_in[15]};
    const float* adst[4] = {(const float*)d_in[4],  (const float*)d_in[8],
                            (const float*)d_in[12], (const float*)d_in[16]};
    const float* bs[4]   = {(const float*)d_in[5],  (const float*)d_in[9],
                            (const float*)d_in[13], (const float*)d_in[17]};

    int N = in_sizes[0] / 256;
    int E = in_sizes[1] / 2;

    float *sb, *db, *smaxb;
    __half *hf;
    __nv_bfloat16 *ah, *wh, *wl;
    cudaGetSymbolAddress((void**)&hf,    g_hf);
    cudaGetSymbolAddress((void**)&sb,    g_s);
    cudaGetSymbolAddress((void**)&db,    g_d);
    cudaGetSymbolAddress((void**)&smaxb, g_smax);
    cudaGetSymbolAddress((void**)&ah,    g_ah);
    cudaGetSymbolAddress((void**)&wh,    g_wh);
    cudaGetSymbolAddress((void**)&wl,    g_wl);

    const int Hs[4]   = {8, 4, 2, 1};
    const int Ks[4]   = {256, 256, 128, 64};
    const int HCs[4]  = {256, 128, 64, 32};
    const int woff[4] = {0, 65536, 98304, 106496};

    // stage = BM*40 (A high) + 2*32*(BN+8) (B h+l); 2 stages, bf16 elems -> bytes
    const int SM1 = (96 * 40 + 2 * 32 * 136) * 2 * 2;    // 50176
    const int SM3 = (128 * 40 + 2 * 32 * 72) * 2 * 2;    // 38912
    const int SM4 = (128 * 40 + 2 * 32 * 40) * 2 * 2;    // 30720
    cudaFuncSetAttribute(gemm_mma_kernel<96, 128, 2, 4, 3>,
                         cudaFuncAttributeMaxDynamicSharedMemorySize, SM1);
    cudaFuncSetAttribute(gemm_mma_kernel<128, 64, 4, 2, 2>,
                         cudaFuncAttributeMaxDynamicSharedMemorySize, SM3);
    cudaFuncSetAttribute(gemm_mma_kernel<128, 32, 8, 1, 1>,
                         cudaFuncAttributeMaxDynamicSharedMemorySize, SM4);

    int gx96 = (N + 95) / 96;
    int gx128 = (N + 127) / 128;
    int aggb = (N + 7) / 8;
    int nb = (N + 511) / 512;

    PrepArgs pa;
    pa.src[0] = x;  pa.oh[0] = ah;  pa.ol[0] = nullptr;    // x: high only
    int acc4 = N * 256 / 4;
    pa.start4[0] = 0;
    for (int L = 0; L < 4; ++L) {
        pa.src[L + 1] = W[L];
        pa.oh[L + 1] = wh + woff[L];
        pa.ol[L + 1] = wl + woff[L];
        pa.start4[L + 1] = acc4;
        acc4 += Ks[L] * HCs[L] / 4;
    }
    pa.total4 = acc4;

    prep_kernel<<<(pa.total4 + 255) / 256, 256>>>(pa);                    // 0
    detzero_kernel<<<(N + 255) / 256, 256>>>((const int*)ei, E, N);       // 1
    hist_kernel<<<(E + 255) / 256, 256>>>(ei, E);                         // 2
    gemm_mma_kernel<96, 128, 2, 4, 3><<<dim3(gx96, 2), 256, SM1>>>(       // 3
        ah, wh, wl, hf, asrc[0], adst[0], sb, db, smaxb, N, 256, 256, 8);
    scan1_kernel<<<nb, 512>>>(N);
    scan2_kernel<<<1, 128>>>(nb, N);
    scan3_kernel<<<nb, 512>>>(N);
    scatter_kernel<<<(E + 255) / 256, 256>>>(ei, E);

    // --- layer 1 aggregation ---
    agg_kernel<8, 0><<<aggb, 256>>>(hf, sb, db, smaxb, bs[0], nullptr, ah, N);

    // --- layers 2-4 ---
    for (int L = 1; L < 4; ++L) {
        int K = Ks[L], HC = HCs[L], H = Hs[L];
        const __nv_bfloat16* whl = wh + woff[L];
        const __nv_bfloat16* wll = wl + woff[L];
        float* smL = smaxb + L * 8;
        if (L == 1)
            gemm_mma_kernel<96, 128, 2, 4, 3><<<dim3(gx96, 1), 256, SM1>>>(
                ah, whl, wll, hf, asrc[L], adst[L], sb, db, smL, N, K, HC, H);
        else if (L == 2)
            gemm_mma_kernel<128, 64, 4, 2, 2><<<dim3(gx128, 1), 256, SM3>>>(
                ah, whl, wll, hf, asrc[L], adst[L], sb, db, smL, N, K, HC, H);
        else
            gemm_mma_kernel<128, 32, 8, 1, 1><<<dim3(gx128, 1), 256, SM4>>>(
                ah, whl, wll, hf, asrc[L], adst[L], sb, db, smL, N, K, HC, H);

        switch (H) {
            case 4:
                agg_kernel<4, 0><<<aggb, 256>>>(hf, sb, db, smL, bs[L],
                                                nullptr, ah, N);
                break;
            case 2:
                agg_kernel<2, 0><<<aggb, 256>>>(hf, sb, db, smL, bs[L],
                                                nullptr, ah, N);
                break;
            default:
                agg_kernel<1, 1><<<aggb, 256>>>(hf, sb, db, smL, bs[L],
                                                (float*)d_out, nullptr, N);
                break;
        }
    }
}